// round 1
// baseline (speedup 1.0000x reference)
#include <cuda_runtime.h>
#include <cuda_bf16.h>
#include <math.h>

// Problem constants
#define L_SEQ 2000
#define D_FEAT 54
#define W_WIN 7
#define H_HEADS 3
#define HD_DIM 18
#define CH_CONV 32
#define CAT_DIM 108        // 2*D
#define K1_DIM 972         // 540 + 324 + 108
#define N1_DIM 256
#define K2_DIM 8192        // 32*256
#define N2_DIM 256

// Scratch (device globals; no allocations allowed)
__device__ float g_f[L_SEQ * D_FEAT];                       // (2000,54)
__device__ float g_cat[L_SEQ * W_WIN * CAT_DIM];            // (2000,7,108)
__device__ float g_feats[(size_t)L_SEQ * CH_CONV * K1_DIM]; // (64000,972) ~249MB
__device__ float g_y1[L_SEQ * K2_DIM];                      // (2000,8192)

// ---------------------------------------------------------------------------
// Kernel A: f = beft @ W_bert + b_bert     (2000,1024)@(1024,54)
// 8 rows per block, 64 threads; row tiles cached in shared.
// ---------------------------------------------------------------------------
__global__ void bert_kernel(const float* __restrict__ beft,
                            const float* __restrict__ Wb,
                            const float* __restrict__ bb,
                            float* __restrict__ f) {
    __shared__ float sh[8][1024];
    int r0 = blockIdx.x * 8;
    for (int idx = threadIdx.x; idx < 8 * 1024; idx += blockDim.x) {
        int r = idx >> 10, c = idx & 1023;
        sh[r][c] = beft[(r0 + r) * 1024 + c];
    }
    __syncthreads();
    int j = threadIdx.x;
    if (j < D_FEAT) {
        float acc[8];
        #pragma unroll
        for (int r = 0; r < 8; r++) acc[r] = 0.f;
        for (int k = 0; k < 1024; k++) {
            float w = Wb[k * D_FEAT + j];
            #pragma unroll
            for (int r = 0; r < 8; r++) acc[r] += sh[r][k] * w;
        }
        float bias = bb[j];
        #pragma unroll
        for (int r = 0; r < 8; r++) f[(r0 + r) * D_FEAT + j] = acc[r] + bias;
    }
}

// ---------------------------------------------------------------------------
// Kernel B: window gather + 2x attention + LN, writes cat=(new_f | sf)
// One block (64 threads) per residue.
// ---------------------------------------------------------------------------
__global__ void attn_kernel(const float* __restrict__ f,
                            const float* __restrict__ g1, const float* __restrict__ be1,
                            const float* __restrict__ g2, const float* __restrict__ be2,
                            float* __restrict__ cat) {
    int i = blockIdx.x;
    int t = threadIdx.x;
    __shared__ float x[W_WIN][D_FEAT];   // current activation
    __shared__ float nf[W_WIN][D_FEAT];  // saved new_f
    __shared__ float p[H_HEADS][W_WIN][W_WIN];
    __shared__ float o[W_WIN][D_FEAT];

    bool boundary = (i <= W_WIN) || (i + W_WIN >= L_SEQ);
    for (int idx = t; idx < W_WIN * D_FEAT; idx += 64) {
        int q = idx / D_FEAT, c = idx % D_FEAT;
        float v;
        if (boundary) v = (q == 0) ? f[i * D_FEAT + c] : 0.f;
        else          v = f[(i - 4 + q) * D_FEAT + c];
        nf[q][c] = v;
        x[q][c] = v;
    }
    __syncthreads();

    for (int pass = 0; pass < 2; pass++) {
        const float* g  = pass ? g2 : g1;
        const float* bb = pass ? be2 : be1;
        // scores s[h][q][k]
        for (int e = t; e < H_HEADS * W_WIN * W_WIN; e += 64) {
            int h = e / 49, rem = e % 49, q = rem / 7, k = rem % 7;
            float s = 0.f;
            #pragma unroll
            for (int d = 0; d < HD_DIM; d++)
                s += x[q][h * HD_DIM + d] * x[k][h * HD_DIM + d];
            p[h][q][k] = s;
        }
        __syncthreads();
        // softmax over k
        if (t < H_HEADS * W_WIN) {
            int h = t / 7, q = t % 7;
            float mx = -1e30f;
            #pragma unroll
            for (int k = 0; k < 7; k++) mx = fmaxf(mx, p[h][q][k]);
            float e[7], sum = 0.f;
            #pragma unroll
            for (int k = 0; k < 7; k++) { e[k] = expf(p[h][q][k] - mx); sum += e[k]; }
            float inv = 1.f / sum;
            #pragma unroll
            for (int k = 0; k < 7; k++) p[h][q][k] = e[k] * inv;
        }
        __syncthreads();
        // o = p @ x
        for (int e = t; e < W_WIN * D_FEAT; e += 64) {
            int q = e / D_FEAT, c = e % D_FEAT, h = c / HD_DIM;
            float s = 0.f;
            #pragma unroll
            for (int k = 0; k < 7; k++) s += p[h][q][k] * x[k][c];
            o[q][c] = s;
        }
        __syncthreads();
        // layernorm per q over 54
        if (t < W_WIN) {
            int q = t;
            float m = 0.f;
            #pragma unroll
            for (int c = 0; c < D_FEAT; c++) m += o[q][c];
            m *= (1.f / D_FEAT);
            float v = 0.f;
            #pragma unroll
            for (int c = 0; c < D_FEAT; c++) { float d = o[q][c] - m; v += d * d; }
            v *= (1.f / D_FEAT);
            float r = rsqrtf(v + 1e-5f);
            #pragma unroll
            for (int c = 0; c < D_FEAT; c++)
                x[q][c] = (o[q][c] - m) * r * g[c] + bb[c];
        }
        __syncthreads();
    }

    // cat = [new_f | sf]
    for (int idx = t; idx < W_WIN * CAT_DIM; idx += 64) {
        int q = idx / CAT_DIM, c = idx % CAT_DIM;
        cat[i * (W_WIN * CAT_DIM) + idx] = (c < D_FEAT) ? nf[q][c] : x[q][c - D_FEAT];
    }
}

// ---------------------------------------------------------------------------
// Kernel C: 3 conv branches + act + maxpool -> feats (64000, 972)
// One block (256 threads) per residue; each thread sweeps (ch,w) pairs.
// ---------------------------------------------------------------------------
__global__ void conv_kernel(const float* __restrict__ cat,
                            const float* __restrict__ cw1, const float* __restrict__ cb1,
                            const float* __restrict__ pa,
                            const float* __restrict__ cw2, const float* __restrict__ cb2,
                            const float* __restrict__ cw3, const float* __restrict__ cb3,
                            float* __restrict__ feats) {
    int i = blockIdx.x;
    int t = threadIdx.x;
    __shared__ float xp[13][CAT_DIM];   // rows -3..9 zero-padded
    __shared__ float w1s[96], w2s[160], w3s[224];
    __shared__ float b1s[32], b2s[32], b3s[32];

    for (int idx = t; idx < 13 * CAT_DIM; idx += 256) {
        int h = idx / CAT_DIM, w = idx % CAT_DIM;
        xp[h][w] = (h >= 3 && h < 10) ? cat[i * (W_WIN * CAT_DIM) + (h - 3) * CAT_DIM + w] : 0.f;
    }
    if (t < 96)  w1s[t] = cw1[t];
    if (t < 160) w2s[t] = cw2[t];
    if (t < 224) w3s[t] = cw3[t];
    if (t < 32) { b1s[t] = cb1[t]; b2s[t] = cb2[t]; b3s[t] = cb3[t]; }
    float a = *pa;
    __syncthreads();

    for (int pair = t; pair < CH_CONV * CAT_DIM; pair += 256) {
        int ch = pair / CAT_DIM, w = pair % CAT_DIM;
        float colp[13];
        #pragma unroll
        for (int h = 0; h < 13; h++) colp[h] = xp[h][w];
        float* fr = &feats[(size_t)i * (CH_CONV * K1_DIM) + ch * K1_DIM];
        float out[7];

        // branch1: k=3, prelu
        {
            const float* wp = &w1s[ch * 3];
            float bb = b1s[ch];
            #pragma unroll
            for (int h = 0; h < 7; h++) {
                float c = bb + wp[0]*colp[h+2] + wp[1]*colp[h+3] + wp[2]*colp[h+4];
                out[h] = (c >= 0.f) ? c : a * c;
            }
            #pragma unroll
            for (int hp = 0; hp < 5; hp++)
                fr[hp * CAT_DIM + w] = fmaxf(fmaxf(out[hp], out[hp+1]), out[hp+2]);
        }
        // branch2: k=5, relu
        {
            const float* wp = &w2s[ch * 5];
            float bb = b2s[ch];
            #pragma unroll
            for (int h = 0; h < 7; h++) {
                float c = bb;
                #pragma unroll
                for (int tt = 0; tt < 5; tt++) c += wp[tt] * colp[h + 1 + tt];
                out[h] = fmaxf(c, 0.f);
            }
            #pragma unroll
            for (int hp = 0; hp < 3; hp++) {
                float m = out[hp];
                #pragma unroll
                for (int q = 1; q < 5; q++) m = fmaxf(m, out[hp + q]);
                fr[540 + hp * CAT_DIM + w] = m;
            }
        }
        // branch3: k=7, relu
        {
            const float* wp = &w3s[ch * 7];
            float bb = b3s[ch];
            float m = -1e30f;
            #pragma unroll
            for (int h = 0; h < 7; h++) {
                float c = bb;
                #pragma unroll
                for (int tt = 0; tt < 7; tt++) c += wp[tt] * colp[h + tt];
                m = fmaxf(m, fmaxf(c, 0.f));
            }
            fr[864 + w] = m;
        }
    }
}

// ---------------------------------------------------------------------------
// Kernel D: GEMM1  C(64000,256) = feats(64000,972) @ W1(972,256) + b1
// 128x128x8 SGEMM, 8x8 per thread, 256 threads.
// ---------------------------------------------------------------------------
__global__ void __launch_bounds__(256) gemm1_kernel(
        const float* __restrict__ A, const float* __restrict__ B,
        const float* __restrict__ bias, float* __restrict__ C) {
    const int N = N1_DIM, K = K1_DIM;
    __shared__ float As[8][132];   // padded, transposed tile
    __shared__ float Bs[8][128];
    int bm = blockIdx.y * 128;
    int bn = blockIdx.x * 128;
    int tid = threadIdx.x;
    int tm = (tid / 16) * 8;
    int tn = (tid % 16) * 8;
    float acc[8][8] = {};
    for (int k0 = 0; k0 < K; k0 += 8) {
        #pragma unroll
        for (int l = 0; l < 4; l++) {
            int idx = tid + l * 256;
            int r = idx >> 3, c = idx & 7;
            As[c][r] = (k0 + c < K) ? A[(size_t)(bm + r) * K + k0 + c] : 0.f;
        }
        #pragma unroll
        for (int l = 0; l < 4; l++) {
            int idx = tid + l * 256;
            int r = idx >> 7, c = idx & 127;
            Bs[r][c] = (k0 + r < K) ? B[(k0 + r) * N + bn + c] : 0.f;
        }
        __syncthreads();
        #pragma unroll
        for (int kk = 0; kk < 8; kk++) {
            float ra[8], rb[8];
            #pragma unroll
            for (int u = 0; u < 8; u++) ra[u] = As[kk][tm + u];
            #pragma unroll
            for (int u = 0; u < 8; u++) rb[u] = Bs[kk][tn + u];
            #pragma unroll
            for (int u = 0; u < 8; u++)
                #pragma unroll
                for (int v = 0; v < 8; v++) acc[u][v] += ra[u] * rb[v];
        }
        __syncthreads();
    }
    #pragma unroll
    for (int u = 0; u < 8; u++) {
        int row = bm + tm + u;
        #pragma unroll
        for (int v = 0; v < 8; v++) {
            int col = bn + tn + v;
            C[(size_t)row * N + col] = acc[u][v] + bias[col];
        }
    }
}

// ---------------------------------------------------------------------------
// Kernel E: GEMM2  out(2000,256) = y1(2000,8192) @ W2(8192,256) + b2, leaky
// 64x64x16 SGEMM, 4x4 per thread, 256 threads.
// ---------------------------------------------------------------------------
__global__ void __launch_bounds__(256) gemm2_kernel(
        const float* __restrict__ A, const float* __restrict__ B,
        const float* __restrict__ bias, float* __restrict__ C) {
    const int M = L_SEQ, N = N2_DIM, K = K2_DIM;
    __shared__ float As[16][68];
    __shared__ float Bs[16][64];
    int bm = blockIdx.y * 64;
    int bn = blockIdx.x * 64;
    int tid = threadIdx.x;
    int tm = (tid / 16) * 4;
    int tn = (tid % 16) * 4;
    float acc[4][4] = {};
    for (int k0 = 0; k0 < K; k0 += 16) {
        #pragma unroll
        for (int l = 0; l < 4; l++) {
            int idx = tid + l * 256;
            int r = idx >> 4, c = idx & 15;
            As[c][r] = (bm + r < M) ? A[(size_t)(bm + r) * K + k0 + c] : 0.f;
        }
        #pragma unroll
        for (int l = 0; l < 4; l++) {
            int idx = tid + l * 256;
            int r = idx >> 6, c = idx & 63;
            Bs[r][c] = B[(k0 + r) * N + bn + c];
        }
        __syncthreads();
        #pragma unroll
        for (int kk = 0; kk < 16; kk++) {
            float ra[4], rb[4];
            #pragma unroll
            for (int u = 0; u < 4; u++) ra[u] = As[kk][tm + u];
            #pragma unroll
            for (int u = 0; u < 4; u++) rb[u] = Bs[kk][tn + u];
            #pragma unroll
            for (int u = 0; u < 4; u++)
                #pragma unroll
                for (int v = 0; v < 4; v++) acc[u][v] += ra[u] * rb[v];
        }
        __syncthreads();
    }
    #pragma unroll
    for (int u = 0; u < 4; u++) {
        int row = bm + tm + u;
        if (row < M) {
            #pragma unroll
            for (int v = 0; v < 4; v++) {
                int col = bn + tn + v;
                float val = acc[u][v] + bias[col];
                C[(size_t)row * N + col] = (val >= 0.f) ? val : 0.01f * val;
            }
        }
    }
}

// ---------------------------------------------------------------------------
extern "C" void kernel_launch(void* const* d_in, const int* in_sizes, int n_in,
                              void* d_out, int out_size) {
    const float* beft   = (const float*)d_in[0];
    // d_in[1..3]: pssm/hmm/dssp — unused by the model
    const float* Wb     = (const float*)d_in[4];
    const float* bb     = (const float*)d_in[5];
    const float* ln_g1  = (const float*)d_in[6];
    const float* ln_b1  = (const float*)d_in[7];
    const float* ln_g2  = (const float*)d_in[8];
    const float* ln_b2  = (const float*)d_in[9];
    const float* cw1    = (const float*)d_in[10];
    const float* cb1    = (const float*)d_in[11];
    const float* pa     = (const float*)d_in[12];
    const float* cw2    = (const float*)d_in[13];
    const float* cb2    = (const float*)d_in[14];
    const float* cw3    = (const float*)d_in[15];
    const float* cb3    = (const float*)d_in[16];
    const float* W1     = (const float*)d_in[17];
    const float* b1     = (const float*)d_in[18];
    const float* W2     = (const float*)d_in[19];
    const float* b2     = (const float*)d_in[20];
    float* out = (float*)d_out;

    float* f     = nullptr; cudaGetSymbolAddress((void**)&f, g_f);
    float* cat   = nullptr; cudaGetSymbolAddress((void**)&cat, g_cat);
    float* feats = nullptr; cudaGetSymbolAddress((void**)&feats, g_feats);
    float* y1    = nullptr; cudaGetSymbolAddress((void**)&y1, g_y1);

    bert_kernel<<<L_SEQ / 8, 64>>>(beft, Wb, bb, f);
    attn_kernel<<<L_SEQ, 64>>>(f, ln_g1, ln_b1, ln_g2, ln_b2, cat);
    conv_kernel<<<L_SEQ, 256>>>(cat, cw1, cb1, pa, cw2, cb2, cw3, cb3, feats);
    {
        dim3 grid(N1_DIM / 128, (L_SEQ * CH_CONV) / 128);  // (2, 500)
        gemm1_kernel<<<grid, 256>>>(feats, W1, b1, y1);
    }
    {
        dim3 grid(N2_DIM / 64, (L_SEQ + 63) / 64);         // (4, 32)
        gemm2_kernel<<<grid, 256>>>(y1, W2, b2, out);
    }
}

// round 2
// speedup vs baseline: 2.5904x; 2.5904x over previous
#include <cuda_runtime.h>
#include <cuda_bf16.h>
#include <cstdint>
#include <math.h>

// Problem constants
#define L_SEQ 2000
#define D_FEAT 54
#define W_WIN 7
#define H_HEADS 3
#define HD_DIM 18
#define CH_CONV 32
#define CAT_DIM 108        // 2*D
#define K1_DIM 972         // 540 + 324 + 108
#define K1P    992         // padded to multiple of 32
#define N_DIM  256
#define K2_DIM 8192        // 32*256

// Scratch (device globals; no allocations allowed)
__device__ float g_f[L_SEQ * D_FEAT];                      // (2000,54)
__device__ float g_cat[L_SEQ * W_WIN * CAT_DIM];           // (2000,7,108)
__device__ float g_feats[(size_t)L_SEQ * CH_CONV * K1P];   // (64000,992) ~254MB, tf32-rounded
__device__ float g_w1p[K1P * N_DIM];                       // padded+rounded W1
__device__ float g_w2r[K2_DIM * N_DIM];                    // rounded W2
__device__ float g_y1[L_SEQ * K2_DIM];                     // (2000,8192) tf32-rounded

__device__ __forceinline__ float tf32r(float x) {
    uint32_t u;
    asm("cvt.rna.tf32.f32 %0, %1;" : "=r"(u) : "f"(x));
    return __uint_as_float(u);
}

// ---------------------------------------------------------------------------
// Prep kernels: pad + tf32-round the GEMM B operands
// ---------------------------------------------------------------------------
__global__ void prep_w1(const float* __restrict__ W1, float* __restrict__ W1p) {
    int idx = blockIdx.x * 256 + threadIdx.x;
    if (idx < K1P * N_DIM) {
        int k = idx / N_DIM;
        W1p[idx] = (k < K1_DIM) ? tf32r(W1[idx]) : 0.f;
    }
}
__global__ void prep_w2(const float* __restrict__ W2, float* __restrict__ W2r) {
    int idx = blockIdx.x * 256 + threadIdx.x;
    if (idx < K2_DIM * N_DIM) W2r[idx] = tf32r(W2[idx]);
}

// ---------------------------------------------------------------------------
// Kernel A: f = beft @ W_bert + b_bert     (2000,1024)@(1024,54)
// ---------------------------------------------------------------------------
__global__ void bert_kernel(const float* __restrict__ beft,
                            const float* __restrict__ Wb,
                            const float* __restrict__ bb,
                            float* __restrict__ f) {
    __shared__ float sh[8][1024];
    int r0 = blockIdx.x * 8;
    for (int idx = threadIdx.x; idx < 8 * 1024; idx += blockDim.x) {
        int r = idx >> 10, c = idx & 1023;
        sh[r][c] = beft[(r0 + r) * 1024 + c];
    }
    __syncthreads();
    int j = threadIdx.x;
    if (j < D_FEAT) {
        float acc[8];
        #pragma unroll
        for (int r = 0; r < 8; r++) acc[r] = 0.f;
        for (int k = 0; k < 1024; k++) {
            float w = Wb[k * D_FEAT + j];
            #pragma unroll
            for (int r = 0; r < 8; r++) acc[r] += sh[r][k] * w;
        }
        float bias = bb[j];
        #pragma unroll
        for (int r = 0; r < 8; r++) f[(r0 + r) * D_FEAT + j] = acc[r] + bias;
    }
}

// ---------------------------------------------------------------------------
// Kernel B: window gather + 2x attention + LN, writes cat=(new_f | sf)
// ---------------------------------------------------------------------------
__global__ void attn_kernel(const float* __restrict__ f,
                            const float* __restrict__ g1, const float* __restrict__ be1,
                            const float* __restrict__ g2, const float* __restrict__ be2,
                            float* __restrict__ cat) {
    int i = blockIdx.x;
    int t = threadIdx.x;
    __shared__ float x[W_WIN][D_FEAT];
    __shared__ float nf[W_WIN][D_FEAT];
    __shared__ float p[H_HEADS][W_WIN][W_WIN];
    __shared__ float o[W_WIN][D_FEAT];

    bool boundary = (i <= W_WIN) || (i + W_WIN >= L_SEQ);
    for (int idx = t; idx < W_WIN * D_FEAT; idx += 64) {
        int q = idx / D_FEAT, c = idx % D_FEAT;
        float v;
        if (boundary) v = (q == 0) ? f[i * D_FEAT + c] : 0.f;
        else          v = f[(i - 4 + q) * D_FEAT + c];
        nf[q][c] = v;
        x[q][c] = v;
    }
    __syncthreads();

    for (int pass = 0; pass < 2; pass++) {
        const float* g  = pass ? g2 : g1;
        const float* bb = pass ? be2 : be1;
        for (int e = t; e < H_HEADS * W_WIN * W_WIN; e += 64) {
            int h = e / 49, rem = e % 49, q = rem / 7, k = rem % 7;
            float s = 0.f;
            #pragma unroll
            for (int d = 0; d < HD_DIM; d++)
                s += x[q][h * HD_DIM + d] * x[k][h * HD_DIM + d];
            p[h][q][k] = s;
        }
        __syncthreads();
        if (t < H_HEADS * W_WIN) {
            int h = t / 7, q = t % 7;
            float mx = -1e30f;
            #pragma unroll
            for (int k = 0; k < 7; k++) mx = fmaxf(mx, p[h][q][k]);
            float e[7], sum = 0.f;
            #pragma unroll
            for (int k = 0; k < 7; k++) { e[k] = expf(p[h][q][k] - mx); sum += e[k]; }
            float inv = 1.f / sum;
            #pragma unroll
            for (int k = 0; k < 7; k++) p[h][q][k] = e[k] * inv;
        }
        __syncthreads();
        for (int e = t; e < W_WIN * D_FEAT; e += 64) {
            int q = e / D_FEAT, c = e % D_FEAT, h = c / HD_DIM;
            float s = 0.f;
            #pragma unroll
            for (int k = 0; k < 7; k++) s += p[h][q][k] * x[k][c];
            o[q][c] = s;
        }
        __syncthreads();
        if (t < W_WIN) {
            int q = t;
            float m = 0.f;
            #pragma unroll
            for (int c = 0; c < D_FEAT; c++) m += o[q][c];
            m *= (1.f / D_FEAT);
            float v = 0.f;
            #pragma unroll
            for (int c = 0; c < D_FEAT; c++) { float d = o[q][c] - m; v += d * d; }
            v *= (1.f / D_FEAT);
            float r = rsqrtf(v + 1e-5f);
            #pragma unroll
            for (int c = 0; c < D_FEAT; c++)
                x[q][c] = (o[q][c] - m) * r * g[c] + bb[c];
        }
        __syncthreads();
    }

    for (int idx = t; idx < W_WIN * CAT_DIM; idx += 64) {
        int q = idx / CAT_DIM, c = idx % CAT_DIM;
        cat[i * (W_WIN * CAT_DIM) + idx] = (c < D_FEAT) ? nf[q][c] : x[q][c - D_FEAT];
    }
}

// ---------------------------------------------------------------------------
// Kernel C: 3 conv branches + act + maxpool -> feats (64000, 992 padded)
// Stores tf32-rounded values; zero-fills pad columns 972..991.
// ---------------------------------------------------------------------------
__global__ void conv_kernel(const float* __restrict__ cat,
                            const float* __restrict__ cw1, const float* __restrict__ cb1,
                            const float* __restrict__ pa,
                            const float* __restrict__ cw2, const float* __restrict__ cb2,
                            const float* __restrict__ cw3, const float* __restrict__ cb3,
                            float* __restrict__ feats) {
    int i = blockIdx.x;
    int t = threadIdx.x;
    __shared__ float xp[13][CAT_DIM];
    __shared__ float w1s[96], w2s[160], w3s[224];
    __shared__ float b1s[32], b2s[32], b3s[32];

    for (int idx = t; idx < 13 * CAT_DIM; idx += 256) {
        int h = idx / CAT_DIM, w = idx % CAT_DIM;
        xp[h][w] = (h >= 3 && h < 10) ? cat[i * (W_WIN * CAT_DIM) + (h - 3) * CAT_DIM + w] : 0.f;
    }
    if (t < 96)  w1s[t] = cw1[t];
    if (t < 160) w2s[t] = cw2[t];
    if (t < 224) w3s[t] = cw3[t];
    if (t < 32) { b1s[t] = cb1[t]; b2s[t] = cb2[t]; b3s[t] = cb3[t]; }
    float a = *pa;
    __syncthreads();

    float* base = &feats[(size_t)i * (CH_CONV * K1P)];

    // zero pad columns
    for (int idx = t; idx < CH_CONV * (K1P - K1_DIM); idx += 256) {
        int ch = idx / (K1P - K1_DIM), c = idx % (K1P - K1_DIM);
        base[ch * K1P + K1_DIM + c] = 0.f;
    }

    for (int pair = t; pair < CH_CONV * CAT_DIM; pair += 256) {
        int ch = pair / CAT_DIM, w = pair % CAT_DIM;
        float colp[13];
        #pragma unroll
        for (int h = 0; h < 13; h++) colp[h] = xp[h][w];
        float* fr = &base[ch * K1P];
        float out[7];

        // branch1: k=3, prelu
        {
            const float* wp = &w1s[ch * 3];
            float bb = b1s[ch];
            #pragma unroll
            for (int h = 0; h < 7; h++) {
                float c = bb + wp[0]*colp[h+2] + wp[1]*colp[h+3] + wp[2]*colp[h+4];
                out[h] = (c >= 0.f) ? c : a * c;
            }
            #pragma unroll
            for (int hp = 0; hp < 5; hp++)
                fr[hp * CAT_DIM + w] = tf32r(fmaxf(fmaxf(out[hp], out[hp+1]), out[hp+2]));
        }
        // branch2: k=5, relu
        {
            const float* wp = &w2s[ch * 5];
            float bb = b2s[ch];
            #pragma unroll
            for (int h = 0; h < 7; h++) {
                float c = bb;
                #pragma unroll
                for (int tt = 0; tt < 5; tt++) c += wp[tt] * colp[h + 1 + tt];
                out[h] = fmaxf(c, 0.f);
            }
            #pragma unroll
            for (int hp = 0; hp < 3; hp++) {
                float m = out[hp];
                #pragma unroll
                for (int q = 1; q < 5; q++) m = fmaxf(m, out[hp + q]);
                fr[540 + hp * CAT_DIM + w] = tf32r(m);
            }
        }
        // branch3: k=7, relu
        {
            const float* wp = &w3s[ch * 7];
            float bb = b3s[ch];
            float m = -1e30f;
            #pragma unroll
            for (int h = 0; h < 7; h++) {
                float c = bb;
                #pragma unroll
                for (int tt = 0; tt < 7; tt++) c += wp[tt] * colp[h + tt];
                m = fmaxf(m, fmaxf(c, 0.f));
            }
            fr[864 + w] = tf32r(m);
        }
    }
}

// ---------------------------------------------------------------------------
// TF32 tensor-core GEMM: C(M,256) = A(M,K) @ B(K,256) + bias [, leaky]
// BM=128, BK=16, 3-stage cp.async pipeline, warp grid 2x4, warp tile 64x(BN/4).
// EPI 0: round output to tf32 (feeds next tf32 GEMM).  EPI 1: leaky-relu.
// A and B must already be tf32-rounded values.
// ---------------------------------------------------------------------------
__device__ __forceinline__ void mma_tf32(float c[4], const uint32_t a[4], const uint32_t b[2]) {
    asm volatile(
        "mma.sync.aligned.m16n8k8.row.col.f32.tf32.tf32.f32 "
        "{%0,%1,%2,%3}, {%4,%5,%6,%7}, {%8,%9}, {%0,%1,%2,%3};\n"
        : "+f"(c[0]), "+f"(c[1]), "+f"(c[2]), "+f"(c[3])
        : "r"(a[0]), "r"(a[1]), "r"(a[2]), "r"(a[3]), "r"(b[0]), "r"(b[1]));
}

template<int BN, int EPI, int KT>
__global__ void __launch_bounds__(256) mma_gemm(
        const float* __restrict__ A, int lda, int M,
        const float* __restrict__ B, const float* __restrict__ bias,
        float* __restrict__ C) {
    constexpr int BM = 128, BK = 16;
    constexpr int WN = BN / 4;      // warp n-tile
    constexpr int NI = WN / 8;      // n8 mma tiles per warp
    __shared__ float sA[3][BM * BK];
    __shared__ float sB[3][BK * BN];

    const int tid = threadIdx.x;
    const int lane = tid & 31, warp = tid >> 5;
    const int bm = blockIdx.y * BM, bn = blockIdx.x * BN;
    const int wm = (warp >> 2) * 64;
    const int wn = (warp & 3) * WN;

    float acc[4][NI][4];
    #pragma unroll
    for (int mi = 0; mi < 4; mi++)
        #pragma unroll
        for (int ni = 0; ni < NI; ni++)
            #pragma unroll
            for (int u = 0; u < 4; u++) acc[mi][ni][u] = 0.f;

    auto loadTile = [&](int kt, int st) {
        int k0 = kt * BK;
        #pragma unroll
        for (int j = 0; j < 2; j++) {
            int ch = tid * 2 + j;                 // 512 chunks: 128 rows x 4
            int r = ch >> 2, c4 = (ch & 3) * 4;
            int gr = min(bm + r, M - 1);
            const float* src = A + (size_t)gr * lda + (k0 + c4);
            uint32_t dst = (uint32_t)__cvta_generic_to_shared(
                &sA[st][r * BK + (c4 ^ (((r >> 1) & 3) << 2))]);
            asm volatile("cp.async.cg.shared.global [%0], [%1], 16;" :: "r"(dst), "l"(src));
        }
        #pragma unroll
        for (int j = 0; j < (BN * BK) / 1024; j++) {
            int ch = tid + j * 256;               // BK*BN/4 chunks
            int k = ch / (BN / 4), n4 = (ch % (BN / 4)) * 4;
            const float* src = B + (size_t)(k0 + k) * N_DIM + bn + n4;
            uint32_t dst = (uint32_t)__cvta_generic_to_shared(
                &sB[st][k * BN + (n4 ^ ((k & 3) << 3))]);
            asm volatile("cp.async.cg.shared.global [%0], [%1], 16;" :: "r"(dst), "l"(src));
        }
    };

    loadTile(0, 0);
    asm volatile("cp.async.commit_group;");
    if (KT > 1) loadTile(1, 1);
    asm volatile("cp.async.commit_group;");

    for (int kt = 0; kt < KT; kt++) {
        if (kt + 2 < KT) {
            loadTile(kt + 2, (kt + 2) % 3);
            asm volatile("cp.async.commit_group;");
            asm volatile("cp.async.wait_group 2;");
        } else if (kt + 2 == KT) {
            asm volatile("cp.async.wait_group 1;");
        } else {
            asm volatile("cp.async.wait_group 0;");
        }
        __syncthreads();

        const int st = kt % 3;
        #pragma unroll
        for (int ks = 0; ks < 2; ks++) {
            uint32_t af[4][4];
            uint32_t bf[NI][2];
            #pragma unroll
            for (int mi = 0; mi < 4; mi++) {
                int r = wm + mi * 16 + (lane >> 2);
                int c = ks * 8 + (lane & 3);
                int sw = ((r >> 1) & 3) << 2;     // same swizzle for r and r+8
                af[mi][0] = *(const uint32_t*)&sA[st][r * BK + (c ^ sw)];
                af[mi][1] = *(const uint32_t*)&sA[st][(r + 8) * BK + (c ^ sw)];
                af[mi][2] = *(const uint32_t*)&sA[st][r * BK + ((c + 4) ^ sw)];
                af[mi][3] = *(const uint32_t*)&sA[st][(r + 8) * BK + ((c + 4) ^ sw)];
            }
            #pragma unroll
            for (int ni = 0; ni < NI; ni++) {
                int n = wn + ni * 8 + (lane >> 2);
                int k = ks * 8 + (lane & 3);
                int sw = (k & 3) << 3;            // same for k and k+4
                bf[ni][0] = *(const uint32_t*)&sB[st][k * BN + (n ^ sw)];
                bf[ni][1] = *(const uint32_t*)&sB[st][(k + 4) * BN + (n ^ sw)];
            }
            #pragma unroll
            for (int mi = 0; mi < 4; mi++)
                #pragma unroll
                for (int ni = 0; ni < NI; ni++)
                    mma_tf32(acc[mi][ni], af[mi], bf[ni]);
        }
        __syncthreads();
    }

    #pragma unroll
    for (int mi = 0; mi < 4; mi++) {
        int row = bm + wm + mi * 16 + (lane >> 2);
        #pragma unroll
        for (int ni = 0; ni < NI; ni++) {
            int col = bn + wn + ni * 8 + (lane & 3) * 2;
            float bv0 = bias[col], bv1 = bias[col + 1];
            float v0 = acc[mi][ni][0] + bv0;
            float v1 = acc[mi][ni][1] + bv1;
            float v2 = acc[mi][ni][2] + bv0;
            float v3 = acc[mi][ni][3] + bv1;
            if (EPI == 0) {
                v0 = tf32r(v0); v1 = tf32r(v1); v2 = tf32r(v2); v3 = tf32r(v3);
            } else {
                v0 = (v0 >= 0.f) ? v0 : 0.01f * v0;
                v1 = (v1 >= 0.f) ? v1 : 0.01f * v1;
                v2 = (v2 >= 0.f) ? v2 : 0.01f * v2;
                v3 = (v3 >= 0.f) ? v3 : 0.01f * v3;
            }
            if (row < M) {
                float2 p0 = make_float2(v0, v1);
                *(float2*)&C[(size_t)row * N_DIM + col] = p0;
            }
            if (row + 8 < M) {
                float2 p1 = make_float2(v2, v3);
                *(float2*)&C[(size_t)(row + 8) * N_DIM + col] = p1;
            }
        }
    }
}

// ---------------------------------------------------------------------------
extern "C" void kernel_launch(void* const* d_in, const int* in_sizes, int n_in,
                              void* d_out, int out_size) {
    const float* beft   = (const float*)d_in[0];
    const float* Wb     = (const float*)d_in[4];
    const float* bb     = (const float*)d_in[5];
    const float* ln_g1  = (const float*)d_in[6];
    const float* ln_b1  = (const float*)d_in[7];
    const float* ln_g2  = (const float*)d_in[8];
    const float* ln_b2  = (const float*)d_in[9];
    const float* cw1    = (const float*)d_in[10];
    const float* cb1    = (const float*)d_in[11];
    const float* pa     = (const float*)d_in[12];
    const float* cw2    = (const float*)d_in[13];
    const float* cb2    = (const float*)d_in[14];
    const float* cw3    = (const float*)d_in[15];
    const float* cb3    = (const float*)d_in[16];
    const float* W1     = (const float*)d_in[17];
    const float* b1     = (const float*)d_in[18];
    const float* W2     = (const float*)d_in[19];
    const float* b2     = (const float*)d_in[20];
    float* out = (float*)d_out;

    float* f     = nullptr; cudaGetSymbolAddress((void**)&f, g_f);
    float* cat   = nullptr; cudaGetSymbolAddress((void**)&cat, g_cat);
    float* feats = nullptr; cudaGetSymbolAddress((void**)&feats, g_feats);
    float* w1p   = nullptr; cudaGetSymbolAddress((void**)&w1p, g_w1p);
    float* w2r   = nullptr; cudaGetSymbolAddress((void**)&w2r, g_w2r);
    float* y1    = nullptr; cudaGetSymbolAddress((void**)&y1, g_y1);

    prep_w1<<<(K1P * N_DIM + 255) / 256, 256>>>(W1, w1p);
    prep_w2<<<(K2_DIM * N_DIM + 255) / 256, 256>>>(W2, w2r);
    bert_kernel<<<L_SEQ / 8, 64>>>(beft, Wb, bb, f);
    attn_kernel<<<L_SEQ, 64>>>(f, ln_g1, ln_b1, ln_g2, ln_b2, cat);
    conv_kernel<<<L_SEQ, 256>>>(cat, cw1, cb1, pa, cw2, cb2, cw3, cb3, feats);

    {   // GEMM1: (64000,992)@(992,256), output tf32-rounded
        dim3 grid(N_DIM / 128, (L_SEQ * CH_CONV) / 128);  // (2, 500)
        mma_gemm<128, 0, K1P / 16><<<grid, 256>>>(feats, K1P, L_SEQ * CH_CONV, w1p, b1, y1);
    }
    {   // GEMM2: (2000,8192)@(8192,256) + leaky
        dim3 grid(N_DIM / 64, (L_SEQ + 127) / 128);       // (4, 16)
        mma_gemm<64, 1, K2_DIM / 16><<<grid, 256>>>(y1, K2_DIM, L_SEQ, w2r, b2, out);
    }
}

// round 3
// speedup vs baseline: 4.6183x; 1.7829x over previous
#include <cuda_runtime.h>
#include <cuda_fp16.h>
#include <cstdint>
#include <math.h>

// Problem constants
#define L_SEQ 2000
#define D_FEAT 54
#define W_WIN 7
#define H_HEADS 3
#define HD_DIM 18
#define CH_CONV 32
#define CAT_DIM 108        // 2*D
#define K1_DIM 972         // real feature dim
#define KF 1024            // padded feature dim
#define N_DIM 256

// Scratch (device globals; no allocations allowed). uint4 for 16B alignment.
__device__ float g_f[L_SEQ * D_FEAT];
__device__ float g_cat[L_SEQ * W_WIN * CAT_DIM];
__device__ uint4 g_featsq[(size_t)CH_CONV * L_SEQ * KF / 8];   // half[32][2000][1024] ~131MB
__device__ uint4 g_w1hq[(size_t)KF * N_DIM / 8];               // half[1024][256]
__device__ uint4 g_w2hq[(size_t)CH_CONV * N_DIM * N_DIM / 8];  // half[8192][256]
__device__ uint4 g_wchq[(size_t)CH_CONV * KF * N_DIM / 8];     // half[32][1024][256]
__device__ float g_ypart[(size_t)CH_CONV * L_SEQ * N_DIM];     // fp32 partials ~65MB
__device__ float g_bcp[CH_CONV * N_DIM];
__device__ float g_bc[N_DIM];

// ---------------------------------------------------------------------------
// Prep: round weights to fp16
// ---------------------------------------------------------------------------
__global__ void round_w1(const float* __restrict__ W1, __half* __restrict__ W1h) {
    int idx = blockIdx.x * 256 + threadIdx.x;
    if (idx < KF * N_DIM) {
        int k = idx >> 8;
        W1h[idx] = (k < K1_DIM) ? __float2half(W1[idx]) : __half(0.f);
    }
}
__global__ void round_w2(const float* __restrict__ W2, __half* __restrict__ W2h) {
    int idx = blockIdx.x * 256 + threadIdx.x;
    if (idx < CH_CONV * N_DIM * N_DIM) W2h[idx] = __float2half(W2[idx]);
}

// bc[n] = b2[n] + sum_{ch,m} b1[m] * W2[ch*256+m, n]
__global__ void bc_partial(const float* __restrict__ b1, const float* __restrict__ W2,
                           float* __restrict__ bcp) {
    int ch = blockIdx.x, n = threadIdx.x;
    float s = 0.f;
    for (int m = 0; m < 256; m++) s += b1[m] * W2[((size_t)ch * 256 + m) * 256 + n];
    bcp[ch * 256 + n] = s;
}
__global__ void bc_final(const float* __restrict__ bcp, const float* __restrict__ b2,
                         float* __restrict__ bc) {
    int n = threadIdx.x;
    float s = b2[n];
    for (int ch = 0; ch < 32; ch++) s += bcp[ch * 256 + n];
    bc[n] = s;
}

// ---------------------------------------------------------------------------
// Kernel A: f = beft @ W_bert + b_bert     (2000,1024)@(1024,54)
// ---------------------------------------------------------------------------
__global__ void bert_kernel(const float* __restrict__ beft,
                            const float* __restrict__ Wb,
                            const float* __restrict__ bb,
                            float* __restrict__ f) {
    __shared__ float sh[8][1024];
    int r0 = blockIdx.x * 8;
    for (int idx = threadIdx.x; idx < 8 * 1024; idx += blockDim.x) {
        int r = idx >> 10, c = idx & 1023;
        sh[r][c] = beft[(r0 + r) * 1024 + c];
    }
    __syncthreads();
    int j = threadIdx.x;
    if (j < D_FEAT) {
        float acc[8];
        #pragma unroll
        for (int r = 0; r < 8; r++) acc[r] = 0.f;
        for (int k = 0; k < 1024; k++) {
            float w = Wb[k * D_FEAT + j];
            #pragma unroll
            for (int r = 0; r < 8; r++) acc[r] += sh[r][k] * w;
        }
        float bias = bb[j];
        #pragma unroll
        for (int r = 0; r < 8; r++) f[(r0 + r) * D_FEAT + j] = acc[r] + bias;
    }
}

// ---------------------------------------------------------------------------
// Kernel B: window gather + 2x attention + LN, writes cat=(new_f | sf)
// ---------------------------------------------------------------------------
__global__ void attn_kernel(const float* __restrict__ f,
                            const float* __restrict__ g1, const float* __restrict__ be1,
                            const float* __restrict__ g2, const float* __restrict__ be2,
                            float* __restrict__ cat) {
    int i = blockIdx.x;
    int t = threadIdx.x;
    __shared__ float x[W_WIN][D_FEAT];
    __shared__ float nf[W_WIN][D_FEAT];
    __shared__ float p[H_HEADS][W_WIN][W_WIN];
    __shared__ float o[W_WIN][D_FEAT];

    bool boundary = (i <= W_WIN) || (i + W_WIN >= L_SEQ);
    for (int idx = t; idx < W_WIN * D_FEAT; idx += 64) {
        int q = idx / D_FEAT, c = idx % D_FEAT;
        float v;
        if (boundary) v = (q == 0) ? f[i * D_FEAT + c] : 0.f;
        else          v = f[(i - 4 + q) * D_FEAT + c];
        nf[q][c] = v;
        x[q][c] = v;
    }
    __syncthreads();

    for (int pass = 0; pass < 2; pass++) {
        const float* g  = pass ? g2 : g1;
        const float* bb = pass ? be2 : be1;
        for (int e = t; e < H_HEADS * W_WIN * W_WIN; e += 64) {
            int h = e / 49, rem = e % 49, q = rem / 7, k = rem % 7;
            float s = 0.f;
            #pragma unroll
            for (int d = 0; d < HD_DIM; d++)
                s += x[q][h * HD_DIM + d] * x[k][h * HD_DIM + d];
            p[h][q][k] = s;
        }
        __syncthreads();
        if (t < H_HEADS * W_WIN) {
            int h = t / 7, q = t % 7;
            float mx = -1e30f;
            #pragma unroll
            for (int k = 0; k < 7; k++) mx = fmaxf(mx, p[h][q][k]);
            float e[7], sum = 0.f;
            #pragma unroll
            for (int k = 0; k < 7; k++) { e[k] = expf(p[h][q][k] - mx); sum += e[k]; }
            float inv = 1.f / sum;
            #pragma unroll
            for (int k = 0; k < 7; k++) p[h][q][k] = e[k] * inv;
        }
        __syncthreads();
        for (int e = t; e < W_WIN * D_FEAT; e += 64) {
            int q = e / D_FEAT, c = e % D_FEAT, h = c / HD_DIM;
            float s = 0.f;
            #pragma unroll
            for (int k = 0; k < 7; k++) s += p[h][q][k] * x[k][c];
            o[q][c] = s;
        }
        __syncthreads();
        if (t < W_WIN) {
            int q = t;
            float m = 0.f;
            #pragma unroll
            for (int c = 0; c < D_FEAT; c++) m += o[q][c];
            m *= (1.f / D_FEAT);
            float v = 0.f;
            #pragma unroll
            for (int c = 0; c < D_FEAT; c++) { float d = o[q][c] - m; v += d * d; }
            v *= (1.f / D_FEAT);
            float r = rsqrtf(v + 1e-5f);
            #pragma unroll
            for (int c = 0; c < D_FEAT; c++)
                x[q][c] = (o[q][c] - m) * r * g[c] + bb[c];
        }
        __syncthreads();
    }

    for (int idx = t; idx < W_WIN * CAT_DIM; idx += 64) {
        int q = idx / CAT_DIM, c = idx % CAT_DIM;
        cat[i * (W_WIN * CAT_DIM) + idx] = (c < D_FEAT) ? nf[q][c] : x[q][c - D_FEAT];
    }
}

// ---------------------------------------------------------------------------
// Kernel C: conv branches + act + maxpool -> feats fp16, layout [ch][i][KF]
// ---------------------------------------------------------------------------
__global__ void conv_kernel(const float* __restrict__ cat,
                            const float* __restrict__ cw1, const float* __restrict__ cb1,
                            const float* __restrict__ pa,
                            const float* __restrict__ cw2, const float* __restrict__ cb2,
                            const float* __restrict__ cw3, const float* __restrict__ cb3,
                            __half* __restrict__ feats) {
    int i = blockIdx.x;
    int t = threadIdx.x;
    __shared__ float xp[13][CAT_DIM];
    __shared__ float w1s[96], w2s[160], w3s[224];
    __shared__ float b1s[32], b2s[32], b3s[32];

    for (int idx = t; idx < 13 * CAT_DIM; idx += 256) {
        int h = idx / CAT_DIM, w = idx % CAT_DIM;
        xp[h][w] = (h >= 3 && h < 10) ? cat[i * (W_WIN * CAT_DIM) + (h - 3) * CAT_DIM + w] : 0.f;
    }
    if (t < 96)  w1s[t] = cw1[t];
    if (t < 160) w2s[t] = cw2[t];
    if (t < 224) w3s[t] = cw3[t];
    if (t < 32) { b1s[t] = cb1[t]; b2s[t] = cb2[t]; b3s[t] = cb3[t]; }
    float a = *pa;
    __syncthreads();

    // zero pad columns 972..1023 for each ch
    for (int idx = t; idx < CH_CONV * (KF - K1_DIM); idx += 256) {
        int ch = idx / (KF - K1_DIM), c = idx % (KF - K1_DIM);
        feats[((size_t)ch * L_SEQ + i) * KF + K1_DIM + c] = __half(0.f);
    }

    for (int pair = t; pair < CH_CONV * CAT_DIM; pair += 256) {
        int ch = pair / CAT_DIM, w = pair % CAT_DIM;
        float colp[13];
        #pragma unroll
        for (int h = 0; h < 13; h++) colp[h] = xp[h][w];
        __half* fr = feats + ((size_t)ch * L_SEQ + i) * KF;
        float out[7];

        // branch1: k=3, prelu, maxpool3 -> rows 0..4
        {
            const float* wp = &w1s[ch * 3];
            float bb = b1s[ch];
            #pragma unroll
            for (int h = 0; h < 7; h++) {
                float c = bb + wp[0]*colp[h+2] + wp[1]*colp[h+3] + wp[2]*colp[h+4];
                out[h] = (c >= 0.f) ? c : a * c;
            }
            #pragma unroll
            for (int hp = 0; hp < 5; hp++)
                fr[hp * CAT_DIM + w] = __float2half(fmaxf(fmaxf(out[hp], out[hp+1]), out[hp+2]));
        }
        // branch2: k=5, relu, maxpool5 -> rows 0..2 (offset 540)
        {
            const float* wp = &w2s[ch * 5];
            float bb = b2s[ch];
            #pragma unroll
            for (int h = 0; h < 7; h++) {
                float c = bb;
                #pragma unroll
                for (int tt = 0; tt < 5; tt++) c += wp[tt] * colp[h + 1 + tt];
                out[h] = fmaxf(c, 0.f);
            }
            #pragma unroll
            for (int hp = 0; hp < 3; hp++) {
                float m = out[hp];
                #pragma unroll
                for (int q = 1; q < 5; q++) m = fmaxf(m, out[hp + q]);
                fr[540 + hp * CAT_DIM + w] = __float2half(m);
            }
        }
        // branch3: k=7, relu, maxpool7 -> 1 row (offset 864)
        {
            const float* wp = &w3s[ch * 7];
            float bb = b3s[ch];
            float m = -1e30f;
            #pragma unroll
            for (int h = 0; h < 7; h++) {
                float c = bb;
                #pragma unroll
                for (int tt = 0; tt < 7; tt++) c += wp[tt] * colp[h + tt];
                m = fmaxf(m, fmaxf(c, 0.f));
            }
            fr[864 + w] = __float2half(m);
        }
    }
}

// ---------------------------------------------------------------------------
// fp16 tensor-core GEMM: C(M,256) = A(M,Kdim) @ B(Kdim,256)
// BM=128, BN=128, BK=32, 2-stage cp.async, ldmatrix, m16n8k16.
// EPI 0: store half to Ch (all rows valid).  EPI 1: store float to Cf, row<Mclamp.
// blockIdx.z selects batch: A += strideA*z, B += strideB*z, C += strideC*z.
// ---------------------------------------------------------------------------
template<int EPI>
__global__ void __launch_bounds__(256) hgemm(
        const __half* __restrict__ A, size_t strideA, int lda, int Mclamp,
        const __half* __restrict__ B, size_t strideB, int KT,
        float* __restrict__ Cf, __half* __restrict__ Ch, size_t strideC) {
    __shared__ __align__(16) __half sA[2][128 * 32];
    __shared__ __align__(16) __half sB[2][32 * 128];
    const int tid = threadIdx.x, lane = tid & 31, warp = tid >> 5;
    const int bn = blockIdx.x * 128, bm = blockIdx.y * 128;
    const int z = blockIdx.z;
    A += strideA * z;
    B += strideB * z;
    const int wm = (warp >> 2) * 64, wn = (warp & 3) * 32;
    uint32_t sAu = (uint32_t)__cvta_generic_to_shared(&sA[0][0]);
    uint32_t sBu = (uint32_t)__cvta_generic_to_shared(&sB[0][0]);

    float acc[4][4][4] = {};

    auto loadTile = [&](int kt, int st) {
        #pragma unroll
        for (int l = 0; l < 2; l++) {
            int j = tid + l * 256;                 // 512 chunks
            int r = j >> 2, c = j & 3;             // row, 16B chunk (8 halves)
            int gr = min(bm + r, Mclamp - 1);
            const __half* src = A + (size_t)gr * lda + kt * 32 + c * 8;
            int cs = c ^ ((r >> 1) & 3);
            uint32_t dst = sAu + (uint32_t)(st * 4096 + r * 32 + cs * 8) * 2;
            asm volatile("cp.async.cg.shared.global [%0], [%1], 16;" :: "r"(dst), "l"(src));
        }
        #pragma unroll
        for (int l = 0; l < 2; l++) {
            int j = tid + l * 256;
            int r = j >> 4, c = j & 15;            // k-row, n-chunk
            const __half* src = B + (size_t)(kt * 32 + r) * N_DIM + bn + c * 8;
            int cs = c ^ (r & 7);
            uint32_t dst = sBu + (uint32_t)(st * 4096 + r * 128 + cs * 8) * 2;
            asm volatile("cp.async.cg.shared.global [%0], [%1], 16;" :: "r"(dst), "l"(src));
        }
    };

    loadTile(0, 0);
    asm volatile("cp.async.commit_group;");
    for (int kt = 0; kt < KT; kt++) {
        if (kt + 1 < KT) {
            loadTile(kt + 1, (kt + 1) & 1);
            asm volatile("cp.async.commit_group;");
            asm volatile("cp.async.wait_group 1;");
        } else {
            asm volatile("cp.async.wait_group 0;");
        }
        __syncthreads();
        const int st = kt & 1;
        #pragma unroll
        for (int ks = 0; ks < 2; ks++) {          // k16 steps within BK=32
            uint32_t a[4][4], b[4][2];
            #pragma unroll
            for (int mi = 0; mi < 4; mi++) {
                int r = wm + mi * 16 + (lane & 15);
                int cc = ks * 2 + (lane >> 4);
                int cs = cc ^ ((r >> 1) & 3);
                uint32_t addr = sAu + (uint32_t)(st * 4096 + r * 32 + cs * 8) * 2;
                asm volatile("ldmatrix.sync.aligned.m8n8.x4.shared.b16 {%0,%1,%2,%3}, [%4];"
                    : "=r"(a[mi][0]), "=r"(a[mi][1]), "=r"(a[mi][2]), "=r"(a[mi][3])
                    : "r"(addr));
            }
            #pragma unroll
            for (int tp = 0; tp < 2; tp++) {
                int kr = ks * 16 + (lane & 15);
                int n0 = wn + (tp * 2 + (lane >> 4)) * 8;
                int cs = (n0 >> 3) ^ (kr & 7);
                uint32_t addr = sBu + (uint32_t)(st * 4096 + kr * 128 + cs * 8) * 2;
                asm volatile("ldmatrix.sync.aligned.m8n8.x4.trans.shared.b16 {%0,%1,%2,%3}, [%4];"
                    : "=r"(b[tp*2][0]), "=r"(b[tp*2][1]), "=r"(b[tp*2+1][0]), "=r"(b[tp*2+1][1])
                    : "r"(addr));
            }
            #pragma unroll
            for (int mi = 0; mi < 4; mi++)
                #pragma unroll
                for (int ni = 0; ni < 4; ni++)
                    asm volatile(
                        "mma.sync.aligned.m16n8k16.row.col.f32.f16.f16.f32 "
                        "{%0,%1,%2,%3}, {%4,%5,%6,%7}, {%8,%9}, {%0,%1,%2,%3};"
                        : "+f"(acc[mi][ni][0]), "+f"(acc[mi][ni][1]),
                          "+f"(acc[mi][ni][2]), "+f"(acc[mi][ni][3])
                        : "r"(a[mi][0]), "r"(a[mi][1]), "r"(a[mi][2]), "r"(a[mi][3]),
                          "r"(b[ni][0]), "r"(b[ni][1]));
        }
        __syncthreads();
    }

    #pragma unroll
    for (int mi = 0; mi < 4; mi++) {
        int r0 = bm + wm + mi * 16 + (lane >> 2);
        #pragma unroll
        for (int ni = 0; ni < 4; ni++) {
            int col = bn + wn + ni * 8 + (lane & 3) * 2;
            if (EPI == 0) {
                __half* base = Ch + strideC * z;
                *(__half2*)(base + (size_t)r0 * N_DIM + col) =
                    __floats2half2_rn(acc[mi][ni][0], acc[mi][ni][1]);
                *(__half2*)(base + (size_t)(r0 + 8) * N_DIM + col) =
                    __floats2half2_rn(acc[mi][ni][2], acc[mi][ni][3]);
            } else {
                float* base = Cf + strideC * z;
                if (r0 < Mclamp) {
                    float2 v = make_float2(acc[mi][ni][0], acc[mi][ni][1]);
                    *(float2*)(base + (size_t)r0 * N_DIM + col) = v;
                }
                if (r0 + 8 < Mclamp) {
                    float2 v = make_float2(acc[mi][ni][2], acc[mi][ni][3]);
                    *(float2*)(base + (size_t)(r0 + 8) * N_DIM + col) = v;
                }
            }
        }
    }
}

// ---------------------------------------------------------------------------
// Reduce over ch + bias + leaky relu
// ---------------------------------------------------------------------------
__global__ void reduce_out(const float* __restrict__ yp, const float* __restrict__ bc,
                           float* __restrict__ out) {
    int idx = blockIdx.x * 256 + threadIdx.x;   // 2000*256
    int n = idx & 255;
    float s = bc[n];
    #pragma unroll
    for (int ch = 0; ch < 32; ch++) s += yp[(size_t)ch * L_SEQ * N_DIM + idx];
    out[idx] = (s >= 0.f) ? s : 0.01f * s;
}

// ---------------------------------------------------------------------------
extern "C" void kernel_launch(void* const* d_in, const int* in_sizes, int n_in,
                              void* d_out, int out_size) {
    const float* beft   = (const float*)d_in[0];
    const float* Wb     = (const float*)d_in[4];
    const float* bb     = (const float*)d_in[5];
    const float* ln_g1  = (const float*)d_in[6];
    const float* ln_b1  = (const float*)d_in[7];
    const float* ln_g2  = (const float*)d_in[8];
    const float* ln_b2  = (const float*)d_in[9];
    const float* cw1    = (const float*)d_in[10];
    const float* cb1    = (const float*)d_in[11];
    const float* pa     = (const float*)d_in[12];
    const float* cw2    = (const float*)d_in[13];
    const float* cb2    = (const float*)d_in[14];
    const float* cw3    = (const float*)d_in[15];
    const float* cb3    = (const float*)d_in[16];
    const float* W1     = (const float*)d_in[17];
    const float* b1     = (const float*)d_in[18];
    const float* W2     = (const float*)d_in[19];
    const float* b2     = (const float*)d_in[20];
    float* out = (float*)d_out;

    float* f   = nullptr; cudaGetSymbolAddress((void**)&f, g_f);
    float* cat = nullptr; cudaGetSymbolAddress((void**)&cat, g_cat);
    __half* feats = nullptr; cudaGetSymbolAddress((void**)&feats, g_featsq);
    __half* w1h   = nullptr; cudaGetSymbolAddress((void**)&w1h, g_w1hq);
    __half* w2h   = nullptr; cudaGetSymbolAddress((void**)&w2h, g_w2hq);
    __half* wch   = nullptr; cudaGetSymbolAddress((void**)&wch, g_wchq);
    float* ypart  = nullptr; cudaGetSymbolAddress((void**)&ypart, g_ypart);
    float* bcp    = nullptr; cudaGetSymbolAddress((void**)&bcp, g_bcp);
    float* bc     = nullptr; cudaGetSymbolAddress((void**)&bc, g_bc);

    // Weight prep
    round_w1<<<(KF * N_DIM + 255) / 256, 256>>>(W1, w1h);
    round_w2<<<(CH_CONV * N_DIM * N_DIM + 255) / 256, 256>>>(W2, w2h);
    bc_partial<<<CH_CONV, 256>>>(b1, W2, bcp);
    bc_final<<<1, 256>>>(bcp, b2, bc);

    // Wc[ch] = W1h(1024x256) @ W2h[ch](256x256), output fp16
    {
        dim3 grid(2, 8, CH_CONV);
        hgemm<0><<<grid, 256>>>(w1h, 0, N_DIM, KF,
                                w2h, (size_t)N_DIM * N_DIM, N_DIM / 32,
                                nullptr, wch, (size_t)KF * N_DIM);
    }

    // Activations
    bert_kernel<<<L_SEQ / 8, 64>>>(beft, Wb, bb, f);
    attn_kernel<<<L_SEQ, 64>>>(f, ln_g1, ln_b1, ln_g2, ln_b2, cat);
    conv_kernel<<<L_SEQ, 256>>>(cat, cw1, cb1, pa, cw2, cb2, cw3, cb3, feats);

    // Main GEMM per ch: ypart[ch] = feats[ch](2000x1024) @ Wc[ch](1024x256)
    {
        dim3 grid(2, 16, CH_CONV);
        hgemm<1><<<grid, 256>>>(feats, (size_t)L_SEQ * KF, KF, L_SEQ,
                                wch, (size_t)KF * N_DIM, KF / 32,
                                ypart, nullptr, (size_t)L_SEQ * N_DIM);
    }

    // out = leaky(sum_ch ypart + bc)
    reduce_out<<<(L_SEQ * N_DIM) / 256, 256>>>(ypart, bc, out);
}

// round 4
// speedup vs baseline: 6.1465x; 1.3309x over previous
#include <cuda_runtime.h>
#include <cuda_fp16.h>
#include <cstdint>
#include <math.h>

// Problem constants
#define L_SEQ 2000
#define D_FEAT 54
#define W_WIN 7
#define H_HEADS 3
#define HD_DIM 18
#define CH_CONV 32
#define CAT_DIM 108        // 2*D
#define K1_DIM 972         // real feature dim
#define KF 1024            // padded feature dim
#define N_DIM 256

// Scratch (device globals; no allocations allowed). uint4 for 16B alignment.
__device__ float g_f[L_SEQ * D_FEAT];
__device__ float g_cat[L_SEQ * W_WIN * CAT_DIM];
__device__ uint4 g_featsq[(size_t)CH_CONV * L_SEQ * KF / 8];   // half[32][2000][1024] ~131MB
__device__ uint4 g_w1hq[(size_t)KF * N_DIM / 8];               // half[1024][256]
__device__ uint4 g_w2hq[(size_t)CH_CONV * N_DIM * N_DIM / 8];  // half[8192][256]
__device__ uint4 g_wchq[(size_t)CH_CONV * KF * N_DIM / 8];     // half[32][1024][256]
__device__ float g_bcp[CH_CONV * N_DIM];

// ---------------------------------------------------------------------------
// Prep: round W1 (padded) and W2 to fp16, one kernel.
// ---------------------------------------------------------------------------
__global__ void prep_weights(const float* __restrict__ W1, __half* __restrict__ W1h,
                             const float* __restrict__ W2, __half* __restrict__ W2h) {
    int idx = blockIdx.x * 256 + threadIdx.x;
    if (idx < KF * N_DIM) {
        int k = idx >> 8;
        W1h[idx] = (k < K1_DIM) ? __float2half(W1[idx]) : __half(0.f);
    }
    int idx2 = idx - KF * N_DIM;
    if (idx2 >= 0 && idx2 < CH_CONV * N_DIM * N_DIM) W2h[idx2] = __float2half(W2[idx2]);
}

// bcp[ch][n] = sum_m b1[m] * W2[ch*256+m, n]
__global__ void bc_partial(const float* __restrict__ b1, const float* __restrict__ W2,
                           float* __restrict__ bcp) {
    int ch = blockIdx.x, n = threadIdx.x;
    float s = 0.f;
    for (int m = 0; m < 256; m++) s += b1[m] * W2[((size_t)ch * 256 + m) * 256 + n];
    bcp[ch * 256 + n] = s;
}

// out[i,n] = b2[n] + sum_ch bcp[ch,n]   (init accumulator with folded bias)
__global__ void init_out(const float* __restrict__ bcp, const float* __restrict__ b2,
                         float* __restrict__ out) {
    int idx = blockIdx.x * 256 + threadIdx.x;
    if (idx < L_SEQ * N_DIM) {
        int n = idx & 255;
        float s = b2[n];
        #pragma unroll
        for (int ch = 0; ch < 32; ch++) s += bcp[ch * 256 + n];
        out[idx] = s;
    }
}

// ---------------------------------------------------------------------------
// Kernel A: f = beft @ W_bert + b_bert     (2000,1024)@(1024,54)
// 4 rows/block, 256 threads: (col 0..63, ksplit 0..3) + smem reduce.
// ---------------------------------------------------------------------------
__global__ void __launch_bounds__(256) bert_kernel(
        const float* __restrict__ beft, const float* __restrict__ Wb,
        const float* __restrict__ bb, float* __restrict__ f) {
    __shared__ float sh[4][1024];
    __shared__ float red[4][4][64];
    int r0 = blockIdx.x * 4;
    int tid = threadIdx.x;
    for (int idx = tid; idx < 4 * 1024; idx += 256)
        sh[idx >> 10][idx & 1023] = beft[(r0 + (idx >> 10)) * 1024 + (idx & 1023)];
    __syncthreads();
    int col = tid & 63;
    int ks = tid >> 6;
    float acc[4] = {0.f, 0.f, 0.f, 0.f};
    if (col < D_FEAT) {
        int kend = ks * 256 + 256;
        for (int k = ks * 256; k < kend; k++) {
            float w = Wb[k * D_FEAT + col];
            #pragma unroll
            for (int r = 0; r < 4; r++) acc[r] += sh[r][k] * w;
        }
    }
    #pragma unroll
    for (int r = 0; r < 4; r++) red[ks][r][col] = acc[r];
    __syncthreads();
    if (ks == 0 && col < D_FEAT) {
        float bias = bb[col];
        #pragma unroll
        for (int r = 0; r < 4; r++)
            f[(r0 + r) * D_FEAT + col] =
                red[0][r][col] + red[1][r][col] + red[2][r][col] + red[3][r][col] + bias;
    }
}

// ---------------------------------------------------------------------------
// Kernel B: warp-per-residue attention (2 passes) -> cat
// 8 warps/block, only __syncwarp barriers.
// ---------------------------------------------------------------------------
__global__ void __launch_bounds__(256) attn_kernel(
        const float* __restrict__ f,
        const float* __restrict__ g1, const float* __restrict__ be1,
        const float* __restrict__ g2, const float* __restrict__ be2,
        float* __restrict__ cat) {
    __shared__ float X[8][W_WIN][D_FEAT];
    __shared__ float NF[8][W_WIN][D_FEAT];
    __shared__ float P[8][H_HEADS][49];
    __shared__ float O[8][W_WIN][D_FEAT];

    int w = threadIdx.x >> 5, lane = threadIdx.x & 31;
    int i = blockIdx.x * 8 + w;
    float (*x)[D_FEAT] = X[w];
    float (*nf)[D_FEAT] = NF[w];
    float (*p)[49] = P[w];
    float (*o)[D_FEAT] = O[w];

    bool boundary = (i <= W_WIN) || (i + W_WIN >= L_SEQ);
    for (int e = lane; e < W_WIN * D_FEAT; e += 32) {
        int q = e / D_FEAT, c = e % D_FEAT;
        float v;
        if (boundary) v = (q == 0) ? f[i * D_FEAT + c] : 0.f;
        else          v = f[(i - 4 + q) * D_FEAT + c];
        x[q][c] = v; nf[q][c] = v;
    }
    __syncwarp();

    #pragma unroll
    for (int pass = 0; pass < 2; pass++) {
        const float* g  = pass ? g2 : g1;
        const float* bb = pass ? be2 : be1;
        // scores
        for (int e = lane; e < H_HEADS * 49; e += 32) {
            int h = e / 49, r = e % 49, q = r / 7, k = r % 7;
            float s = 0.f;
            #pragma unroll
            for (int d = 0; d < HD_DIM; d++)
                s += x[q][h * HD_DIM + d] * x[k][h * HD_DIM + d];
            p[h][r] = s;
        }
        __syncwarp();
        // softmax over k (21 rows)
        if (lane < H_HEADS * W_WIN) {
            int h = lane / 7, q = lane % 7;
            float* pr = &p[h][q * 7];
            float mx = -1e30f;
            #pragma unroll
            for (int k = 0; k < 7; k++) mx = fmaxf(mx, pr[k]);
            float e[7], sum = 0.f;
            #pragma unroll
            for (int k = 0; k < 7; k++) { e[k] = expf(pr[k] - mx); sum += e[k]; }
            float inv = 1.f / sum;
            #pragma unroll
            for (int k = 0; k < 7; k++) pr[k] = e[k] * inv;
        }
        __syncwarp();
        // o = p @ x
        for (int e = lane; e < W_WIN * D_FEAT; e += 32) {
            int q = e / D_FEAT, c = e % D_FEAT, h = c / HD_DIM;
            const float* pr = &p[h][q * 7];
            float s = 0.f;
            #pragma unroll
            for (int k = 0; k < 7; k++) s += pr[k] * x[k][c];
            o[q][c] = s;
        }
        __syncwarp();
        // layernorm per q
        if (lane < W_WIN) {
            int q = lane;
            float m = 0.f;
            #pragma unroll
            for (int c = 0; c < D_FEAT; c++) m += o[q][c];
            m *= (1.f / D_FEAT);
            float v = 0.f;
            #pragma unroll
            for (int c = 0; c < D_FEAT; c++) { float d = o[q][c] - m; v += d * d; }
            v *= (1.f / D_FEAT);
            float r = rsqrtf(v + 1e-5f);
            #pragma unroll
            for (int c = 0; c < D_FEAT; c++)
                x[q][c] = (o[q][c] - m) * r * g[c] + bb[c];
        }
        __syncwarp();
    }

    for (int e = lane; e < W_WIN * CAT_DIM; e += 32) {
        int q = e / CAT_DIM, c = e % CAT_DIM;
        cat[i * (W_WIN * CAT_DIM) + e] = (c < D_FEAT) ? nf[q][c] : x[q][c - D_FEAT];
    }
}

// ---------------------------------------------------------------------------
// Kernel C: conv branches + act + maxpool -> feats fp16, layout [ch][i][KF]
// ---------------------------------------------------------------------------
__global__ void conv_kernel(const float* __restrict__ cat,
                            const float* __restrict__ cw1, const float* __restrict__ cb1,
                            const float* __restrict__ pa,
                            const float* __restrict__ cw2, const float* __restrict__ cb2,
                            const float* __restrict__ cw3, const float* __restrict__ cb3,
                            __half* __restrict__ feats) {
    int i = blockIdx.x;
    int t = threadIdx.x;
    __shared__ float xp[13][CAT_DIM];
    __shared__ float w1s[96], w2s[160], w3s[224];
    __shared__ float b1s[32], b2s[32], b3s[32];

    for (int idx = t; idx < 13 * CAT_DIM; idx += 256) {
        int h = idx / CAT_DIM, w = idx % CAT_DIM;
        xp[h][w] = (h >= 3 && h < 10) ? cat[i * (W_WIN * CAT_DIM) + (h - 3) * CAT_DIM + w] : 0.f;
    }
    if (t < 96)  w1s[t] = cw1[t];
    if (t < 160) w2s[t] = cw2[t];
    if (t < 224) w3s[t] = cw3[t];
    if (t < 32) { b1s[t] = cb1[t]; b2s[t] = cb2[t]; b3s[t] = cb3[t]; }
    float a = *pa;
    __syncthreads();

    // zero pad columns 972..1023 for each ch
    for (int idx = t; idx < CH_CONV * (KF - K1_DIM); idx += 256) {
        int ch = idx / (KF - K1_DIM), c = idx % (KF - K1_DIM);
        feats[((size_t)ch * L_SEQ + i) * KF + K1_DIM + c] = __half(0.f);
    }

    for (int pair = t; pair < CH_CONV * CAT_DIM; pair += 256) {
        int ch = pair / CAT_DIM, w = pair % CAT_DIM;
        float colp[13];
        #pragma unroll
        for (int h = 0; h < 13; h++) colp[h] = xp[h][w];
        __half* fr = feats + ((size_t)ch * L_SEQ + i) * KF;
        float out[7];

        // branch1: k=3, prelu, maxpool3 -> rows 0..4
        {
            const float* wp = &w1s[ch * 3];
            float bb = b1s[ch];
            #pragma unroll
            for (int h = 0; h < 7; h++) {
                float c = bb + wp[0]*colp[h+2] + wp[1]*colp[h+3] + wp[2]*colp[h+4];
                out[h] = (c >= 0.f) ? c : a * c;
            }
            #pragma unroll
            for (int hp = 0; hp < 5; hp++)
                fr[hp * CAT_DIM + w] = __float2half(fmaxf(fmaxf(out[hp], out[hp+1]), out[hp+2]));
        }
        // branch2: k=5, relu, maxpool5 -> rows 0..2 (offset 540)
        {
            const float* wp = &w2s[ch * 5];
            float bb = b2s[ch];
            #pragma unroll
            for (int h = 0; h < 7; h++) {
                float c = bb;
                #pragma unroll
                for (int tt = 0; tt < 5; tt++) c += wp[tt] * colp[h + 1 + tt];
                out[h] = fmaxf(c, 0.f);
            }
            #pragma unroll
            for (int hp = 0; hp < 3; hp++) {
                float m = out[hp];
                #pragma unroll
                for (int q = 1; q < 5; q++) m = fmaxf(m, out[hp + q]);
                fr[540 + hp * CAT_DIM + w] = __float2half(m);
            }
        }
        // branch3: k=7, relu, maxpool7 -> 1 row (offset 864)
        {
            const float* wp = &w3s[ch * 7];
            float bb = b3s[ch];
            float m = -1e30f;
            #pragma unroll
            for (int h = 0; h < 7; h++) {
                float c = bb;
                #pragma unroll
                for (int tt = 0; tt < 7; tt++) c += wp[tt] * colp[h + tt];
                m = fmaxf(m, fmaxf(c, 0.f));
            }
            fr[864 + w] = __float2half(m);
        }
    }
}

// ---------------------------------------------------------------------------
// fp16 tensor-core GEMM: C(M,256) = A(M,Kdim) @ B(Kdim,256)
// BM=128, BN=128, BK=32, 3-stage cp.async, ldmatrix, m16n8k16.
// EPI 0: store half to Ch (all rows valid).
// EPI 1: atomicAdd float into Cf (shared across z), row<Mclamp.
// blockIdx.z selects batch: A += strideA*z, B += strideB*z, C += strideC*z.
// ---------------------------------------------------------------------------
template<int EPI>
__global__ void __launch_bounds__(256) hgemm(
        const __half* __restrict__ A, size_t strideA, int lda, int Mclamp,
        const __half* __restrict__ B, size_t strideB, int KT,
        float* __restrict__ Cf, __half* __restrict__ Ch, size_t strideC) {
    __shared__ __align__(16) __half sA[3][128 * 32];
    __shared__ __align__(16) __half sB[3][32 * 128];
    const int tid = threadIdx.x, lane = tid & 31, warp = tid >> 5;
    const int bn = blockIdx.x * 128, bm = blockIdx.y * 128;
    const int z = blockIdx.z;
    A += strideA * z;
    B += strideB * z;
    const int wm = (warp >> 2) * 64, wn = (warp & 3) * 32;
    uint32_t sAu = (uint32_t)__cvta_generic_to_shared(&sA[0][0]);
    uint32_t sBu = (uint32_t)__cvta_generic_to_shared(&sB[0][0]);

    float acc[4][4][4] = {};

    auto loadTile = [&](int kt, int st) {
        #pragma unroll
        for (int l = 0; l < 2; l++) {
            int j = tid + l * 256;                 // 512 chunks
            int r = j >> 2, c = j & 3;             // row, 16B chunk (8 halves)
            int gr = min(bm + r, Mclamp - 1);
            const __half* src = A + (size_t)gr * lda + kt * 32 + c * 8;
            int cs = c ^ ((r >> 1) & 3);
            uint32_t dst = sAu + (uint32_t)(st * 4096 + r * 32 + cs * 8) * 2;
            asm volatile("cp.async.cg.shared.global [%0], [%1], 16;" :: "r"(dst), "l"(src));
        }
        #pragma unroll
        for (int l = 0; l < 2; l++) {
            int j = tid + l * 256;
            int r = j >> 4, c = j & 15;            // k-row, n-chunk
            const __half* src = B + (size_t)(kt * 32 + r) * N_DIM + bn + c * 8;
            int cs = c ^ (r & 7);
            uint32_t dst = sBu + (uint32_t)(st * 4096 + r * 128 + cs * 8) * 2;
            asm volatile("cp.async.cg.shared.global [%0], [%1], 16;" :: "r"(dst), "l"(src));
        }
    };

    loadTile(0, 0);
    asm volatile("cp.async.commit_group;");
    loadTile(1, 1);
    asm volatile("cp.async.commit_group;");

    for (int kt = 0; kt < KT; kt++) {
        if (kt + 2 < KT) {
            loadTile(kt + 2, (kt + 2) % 3);
            asm volatile("cp.async.commit_group;");
            asm volatile("cp.async.wait_group 2;");
        } else if (kt + 2 == KT) {
            asm volatile("cp.async.wait_group 1;");
        } else {
            asm volatile("cp.async.wait_group 0;");
        }
        __syncthreads();
        const int st = kt % 3;
        #pragma unroll
        for (int ks = 0; ks < 2; ks++) {          // k16 steps within BK=32
            uint32_t a[4][4], b[4][2];
            #pragma unroll
            for (int mi = 0; mi < 4; mi++) {
                int r = wm + mi * 16 + (lane & 15);
                int cc = ks * 2 + (lane >> 4);
                int cs = cc ^ ((r >> 1) & 3);
                uint32_t addr = sAu + (uint32_t)(st * 4096 + r * 32 + cs * 8) * 2;
                asm volatile("ldmatrix.sync.aligned.m8n8.x4.shared.b16 {%0,%1,%2,%3}, [%4];"
                    : "=r"(a[mi][0]), "=r"(a[mi][1]), "=r"(a[mi][2]), "=r"(a[mi][3])
                    : "r"(addr));
            }
            #pragma unroll
            for (int tp = 0; tp < 2; tp++) {
                int kr = ks * 16 + (lane & 15);
                int n0 = wn + (tp * 2 + (lane >> 4)) * 8;
                int cs = (n0 >> 3) ^ (kr & 7);
                uint32_t addr = sBu + (uint32_t)(st * 4096 + kr * 128 + cs * 8) * 2;
                asm volatile("ldmatrix.sync.aligned.m8n8.x4.trans.shared.b16 {%0,%1,%2,%3}, [%4];"
                    : "=r"(b[tp*2][0]), "=r"(b[tp*2][1]), "=r"(b[tp*2+1][0]), "=r"(b[tp*2+1][1])
                    : "r"(addr));
            }
            #pragma unroll
            for (int mi = 0; mi < 4; mi++)
                #pragma unroll
                for (int ni = 0; ni < 4; ni++)
                    asm volatile(
                        "mma.sync.aligned.m16n8k16.row.col.f32.f16.f16.f32 "
                        "{%0,%1,%2,%3}, {%4,%5,%6,%7}, {%8,%9}, {%0,%1,%2,%3};"
                        : "+f"(acc[mi][ni][0]), "+f"(acc[mi][ni][1]),
                          "+f"(acc[mi][ni][2]), "+f"(acc[mi][ni][3])
                        : "r"(a[mi][0]), "r"(a[mi][1]), "r"(a[mi][2]), "r"(a[mi][3]),
                          "r"(b[ni][0]), "r"(b[ni][1]));
        }
        __syncthreads();
    }

    #pragma unroll
    for (int mi = 0; mi < 4; mi++) {
        int r0 = bm + wm + mi * 16 + (lane >> 2);
        #pragma unroll
        for (int ni = 0; ni < 4; ni++) {
            int col = bn + wn + ni * 8 + (lane & 3) * 2;
            if (EPI == 0) {
                __half* base = Ch + strideC * z;
                *(__half2*)(base + (size_t)r0 * N_DIM + col) =
                    __floats2half2_rn(acc[mi][ni][0], acc[mi][ni][1]);
                *(__half2*)(base + (size_t)(r0 + 8) * N_DIM + col) =
                    __floats2half2_rn(acc[mi][ni][2], acc[mi][ni][3]);
            } else {
                if (r0 < Mclamp) {
                    atomicAdd(&Cf[(size_t)r0 * N_DIM + col],     acc[mi][ni][0]);
                    atomicAdd(&Cf[(size_t)r0 * N_DIM + col + 1], acc[mi][ni][1]);
                }
                if (r0 + 8 < Mclamp) {
                    atomicAdd(&Cf[(size_t)(r0 + 8) * N_DIM + col],     acc[mi][ni][2]);
                    atomicAdd(&Cf[(size_t)(r0 + 8) * N_DIM + col + 1], acc[mi][ni][3]);
                }
            }
        }
    }
}

// ---------------------------------------------------------------------------
// Final: in-place leaky relu on out
// ---------------------------------------------------------------------------
__global__ void leaky_inplace(float* __restrict__ out) {
    int idx = blockIdx.x * 256 + threadIdx.x;
    if (idx < L_SEQ * N_DIM) {
        float s = out[idx];
        out[idx] = (s >= 0.f) ? s : 0.01f * s;
    }
}

// ---------------------------------------------------------------------------
extern "C" void kernel_launch(void* const* d_in, const int* in_sizes, int n_in,
                              void* d_out, int out_size) {
    const float* beft   = (const float*)d_in[0];
    const float* Wb     = (const float*)d_in[4];
    const float* bb     = (const float*)d_in[5];
    const float* ln_g1  = (const float*)d_in[6];
    const float* ln_b1  = (const float*)d_in[7];
    const float* ln_g2  = (const float*)d_in[8];
    const float* ln_b2  = (const float*)d_in[9];
    const float* cw1    = (const float*)d_in[10];
    const float* cb1    = (const float*)d_in[11];
    const float* pa     = (const float*)d_in[12];
    const float* cw2    = (const float*)d_in[13];
    const float* cb2    = (const float*)d_in[14];
    const float* cw3    = (const float*)d_in[15];
    const float* cb3    = (const float*)d_in[16];
    const float* W1     = (const float*)d_in[17];
    const float* b1     = (const float*)d_in[18];
    const float* W2     = (const float*)d_in[19];
    const float* b2     = (const float*)d_in[20];
    float* out = (float*)d_out;

    float* f   = nullptr; cudaGetSymbolAddress((void**)&f, g_f);
    float* cat = nullptr; cudaGetSymbolAddress((void**)&cat, g_cat);
    __half* feats = nullptr; cudaGetSymbolAddress((void**)&feats, g_featsq);
    __half* w1h   = nullptr; cudaGetSymbolAddress((void**)&w1h, g_w1hq);
    __half* w2h   = nullptr; cudaGetSymbolAddress((void**)&w2h, g_w2hq);
    __half* wch   = nullptr; cudaGetSymbolAddress((void**)&wch, g_wchq);
    float* bcp    = nullptr; cudaGetSymbolAddress((void**)&bcp, g_bcp);

    // Weight prep + bias folding + out init
    {
        int total = KF * N_DIM + CH_CONV * N_DIM * N_DIM;
        prep_weights<<<(total + 255) / 256, 256>>>(W1, w1h, W2, w2h);
    }
    bc_partial<<<CH_CONV, 256>>>(b1, W2, bcp);
    init_out<<<(L_SEQ * N_DIM + 255) / 256, 256>>>(bcp, b2, out);

    // Wc[ch] = W1h(1024x256) @ W2h[ch](256x256), output fp16
    {
        dim3 grid(2, 8, CH_CONV);
        hgemm<0><<<grid, 256>>>(w1h, 0, N_DIM, KF,
                                w2h, (size_t)N_DIM * N_DIM, N_DIM / 32,
                                nullptr, wch, (size_t)KF * N_DIM);
    }

    // Activations
    bert_kernel<<<L_SEQ / 4, 256>>>(beft, Wb, bb, f);
    attn_kernel<<<L_SEQ / 8, 256>>>(f, ln_g1, ln_b1, ln_g2, ln_b2, cat);
    conv_kernel<<<L_SEQ, 256>>>(cat, cw1, cb1, pa, cw2, cb2, cw3, cb3, feats);

    // Main GEMM per ch: out += feats[ch](2000x1024) @ Wc[ch](1024x256)
    {
        dim3 grid(2, 16, CH_CONV);
        hgemm<1><<<grid, 256>>>(feats, (size_t)L_SEQ * KF, KF, L_SEQ,
                                wch, (size_t)KF * N_DIM, KF / 32,
                                out, nullptr, 0);
    }

    // out = leaky(out)
    leaky_inplace<<<(L_SEQ * N_DIM + 255) / 256, 256>>>(out);
}

// round 5
// speedup vs baseline: 6.6066x; 1.0748x over previous
#include <cuda_runtime.h>
#include <cuda_fp16.h>
#include <cstdint>
#include <math.h>

// Problem constants
#define L_SEQ 2000
#define D_FEAT 54
#define W_WIN 7
#define H_HEADS 3
#define HD_DIM 18
#define CH_CONV 32
#define CAT_DIM 108        // 2*D
#define K1_DIM 972         // real feature dim
#define KF 1024            // padded feature dim
#define N_DIM 256

// Scratch (device globals; no allocations allowed). uint4 for 16B alignment.
__device__ float g_f[L_SEQ * D_FEAT];
__device__ float g_cat[L_SEQ * W_WIN * CAT_DIM];
__device__ uint4 g_featsq[(size_t)CH_CONV * L_SEQ * KF / 8];   // half[32][2000][1024] ~131MB
__device__ uint4 g_w1hq[(size_t)KF * N_DIM / 8];               // half[1024][256]
__device__ uint4 g_w2hq[(size_t)CH_CONV * N_DIM * N_DIM / 8];  // half[8192][256]
__device__ uint4 g_wchq[(size_t)CH_CONV * KF * N_DIM / 8];     // half[32][1024][256]
__device__ float g_bcp[CH_CONV * N_DIM];

// ---------------------------------------------------------------------------
// Prep: round W1 (padded) and W2 to fp16, one kernel.
// ---------------------------------------------------------------------------
__global__ void prep_weights(const float* __restrict__ W1, __half* __restrict__ W1h,
                             const float* __restrict__ W2, __half* __restrict__ W2h) {
    int idx = blockIdx.x * 256 + threadIdx.x;
    if (idx < KF * N_DIM) {
        int k = idx >> 8;
        W1h[idx] = (k < K1_DIM) ? __float2half(W1[idx]) : __half(0.f);
    }
    int idx2 = idx - KF * N_DIM;
    if (idx2 >= 0 && idx2 < CH_CONV * N_DIM * N_DIM) W2h[idx2] = __float2half(W2[idx2]);
}

// bcp[ch][n] = sum_m b1[m] * W2[ch*256+m, n]
__global__ void bc_partial(const float* __restrict__ b1, const float* __restrict__ W2,
                           float* __restrict__ bcp) {
    int ch = blockIdx.x, n = threadIdx.x;
    float s = 0.f;
    for (int m = 0; m < 256; m++) s += b1[m] * W2[((size_t)ch * 256 + m) * 256 + n];
    bcp[ch * 256 + n] = s;
}

// out[i,n] = b2[n] + sum_ch bcp[ch,n]   (init accumulator with folded bias)
__global__ void init_out(const float* __restrict__ bcp, const float* __restrict__ b2,
                         float* __restrict__ out) {
    int idx = blockIdx.x * 256 + threadIdx.x;
    if (idx < L_SEQ * N_DIM) {
        int n = idx & 255;
        float s = b2[n];
        #pragma unroll
        for (int ch = 0; ch < 32; ch++) s += bcp[ch * 256 + n];
        out[idx] = s;
    }
}

// ---------------------------------------------------------------------------
// Kernel A: f = beft @ W_bert + b_bert     (2000,1024)@(1024,54)
// ---------------------------------------------------------------------------
__global__ void __launch_bounds__(256) bert_kernel(
        const float* __restrict__ beft, const float* __restrict__ Wb,
        const float* __restrict__ bb, float* __restrict__ f) {
    __shared__ float sh[4][1024];
    __shared__ float red[4][4][64];
    int r0 = blockIdx.x * 4;
    int tid = threadIdx.x;
    for (int idx = tid; idx < 4 * 1024; idx += 256)
        sh[idx >> 10][idx & 1023] = beft[(r0 + (idx >> 10)) * 1024 + (idx & 1023)];
    __syncthreads();
    int col = tid & 63;
    int ks = tid >> 6;
    float acc[4] = {0.f, 0.f, 0.f, 0.f};
    if (col < D_FEAT) {
        int kend = ks * 256 + 256;
        for (int k = ks * 256; k < kend; k++) {
            float w = Wb[k * D_FEAT + col];
            #pragma unroll
            for (int r = 0; r < 4; r++) acc[r] += sh[r][k] * w;
        }
    }
    #pragma unroll
    for (int r = 0; r < 4; r++) red[ks][r][col] = acc[r];
    __syncthreads();
    if (ks == 0 && col < D_FEAT) {
        float bias = bb[col];
        #pragma unroll
        for (int r = 0; r < 4; r++)
            f[(r0 + r) * D_FEAT + col] =
                red[0][r][col] + red[1][r][col] + red[2][r][col] + red[3][r][col] + bias;
    }
}

// ---------------------------------------------------------------------------
// Kernel B: warp-per-residue attention (2 passes) -> cat
// ---------------------------------------------------------------------------
__global__ void __launch_bounds__(256) attn_kernel(
        const float* __restrict__ f,
        const float* __restrict__ g1, const float* __restrict__ be1,
        const float* __restrict__ g2, const float* __restrict__ be2,
        float* __restrict__ cat) {
    __shared__ float X[8][W_WIN][D_FEAT];
    __shared__ float NF[8][W_WIN][D_FEAT];
    __shared__ float P[8][H_HEADS][49];
    __shared__ float O[8][W_WIN][D_FEAT];

    int w = threadIdx.x >> 5, lane = threadIdx.x & 31;
    int i = blockIdx.x * 8 + w;
    float (*x)[D_FEAT] = X[w];
    float (*nf)[D_FEAT] = NF[w];
    float (*p)[49] = P[w];
    float (*o)[D_FEAT] = O[w];

    bool boundary = (i <= W_WIN) || (i + W_WIN >= L_SEQ);
    for (int e = lane; e < W_WIN * D_FEAT; e += 32) {
        int q = e / D_FEAT, c = e % D_FEAT;
        float v;
        if (boundary) v = (q == 0) ? f[i * D_FEAT + c] : 0.f;
        else          v = f[(i - 4 + q) * D_FEAT + c];
        x[q][c] = v; nf[q][c] = v;
    }
    __syncwarp();

    #pragma unroll
    for (int pass = 0; pass < 2; pass++) {
        const float* g  = pass ? g2 : g1;
        const float* bb = pass ? be2 : be1;
        for (int e = lane; e < H_HEADS * 49; e += 32) {
            int h = e / 49, r = e % 49, q = r / 7, k = r % 7;
            float s = 0.f;
            #pragma unroll
            for (int d = 0; d < HD_DIM; d++)
                s += x[q][h * HD_DIM + d] * x[k][h * HD_DIM + d];
            p[h][r] = s;
        }
        __syncwarp();
        if (lane < H_HEADS * W_WIN) {
            int h = lane / 7, q = lane % 7;
            float* pr = &p[h][q * 7];
            float mx = -1e30f;
            #pragma unroll
            for (int k = 0; k < 7; k++) mx = fmaxf(mx, pr[k]);
            float e[7], sum = 0.f;
            #pragma unroll
            for (int k = 0; k < 7; k++) { e[k] = expf(pr[k] - mx); sum += e[k]; }
            float inv = 1.f / sum;
            #pragma unroll
            for (int k = 0; k < 7; k++) pr[k] = e[k] * inv;
        }
        __syncwarp();
        for (int e = lane; e < W_WIN * D_FEAT; e += 32) {
            int q = e / D_FEAT, c = e % D_FEAT, h = c / HD_DIM;
            const float* pr = &p[h][q * 7];
            float s = 0.f;
            #pragma unroll
            for (int k = 0; k < 7; k++) s += pr[k] * x[k][c];
            o[q][c] = s;
        }
        __syncwarp();
        if (lane < W_WIN) {
            int q = lane;
            float m = 0.f;
            #pragma unroll
            for (int c = 0; c < D_FEAT; c++) m += o[q][c];
            m *= (1.f / D_FEAT);
            float v = 0.f;
            #pragma unroll
            for (int c = 0; c < D_FEAT; c++) { float d = o[q][c] - m; v += d * d; }
            v *= (1.f / D_FEAT);
            float r = rsqrtf(v + 1e-5f);
            #pragma unroll
            for (int c = 0; c < D_FEAT; c++)
                x[q][c] = (o[q][c] - m) * r * g[c] + bb[c];
        }
        __syncwarp();
    }

    for (int e = lane; e < W_WIN * CAT_DIM; e += 32) {
        int q = e / CAT_DIM, c = e % CAT_DIM;
        cat[i * (W_WIN * CAT_DIM) + e] = (c < D_FEAT) ? nf[q][c] : x[q][c - D_FEAT];
    }
}

// ---------------------------------------------------------------------------
// Kernel C: conv branches + act + maxpool -> feats fp16, layout [ch][i][KF]
// Processes column PAIRS, stores half2 (better store throughput).
// ---------------------------------------------------------------------------
__global__ void __launch_bounds__(256) conv_kernel(
        const float* __restrict__ cat,
        const float* __restrict__ cw1, const float* __restrict__ cb1,
        const float* __restrict__ pa,
        const float* __restrict__ cw2, const float* __restrict__ cb2,
        const float* __restrict__ cw3, const float* __restrict__ cb3,
        __half* __restrict__ feats) {
    int i = blockIdx.x;
    int t = threadIdx.x;
    __shared__ float xp[13][CAT_DIM];
    __shared__ float w1s[96], w2s[160], w3s[224];
    __shared__ float b1s[32], b2s[32], b3s[32];

    for (int idx = t; idx < 13 * CAT_DIM; idx += 256) {
        int h = idx / CAT_DIM, w = idx % CAT_DIM;
        xp[h][w] = (h >= 3 && h < 10) ? cat[i * (W_WIN * CAT_DIM) + (h - 3) * CAT_DIM + w] : 0.f;
    }
    if (t < 96)  w1s[t] = cw1[t];
    if (t < 160) w2s[t] = cw2[t];
    if (t < 224) w3s[t] = cw3[t];
    if (t < 32) { b1s[t] = cb1[t]; b2s[t] = cb2[t]; b3s[t] = cb3[t]; }
    float a = *pa;
    __syncthreads();

    // zero pad columns 972..1023 for each ch (half2 strided)
    for (int idx = t; idx < CH_CONV * (KF - K1_DIM) / 2; idx += 256) {
        int ch = idx / 26, c = idx % 26;
        *(__half2*)&feats[((size_t)ch * L_SEQ + i) * KF + K1_DIM + c * 2] =
            __floats2half2_rn(0.f, 0.f);
    }

    // 32 ch * 54 col-pairs = 1728 work items
    for (int pp = t; pp < CH_CONV * (CAT_DIM / 2); pp += 256) {
        int ch = pp / (CAT_DIM / 2), w = (pp % (CAT_DIM / 2)) * 2;
        float c0[13], c1[13];
        #pragma unroll
        for (int h = 0; h < 13; h++) { c0[h] = xp[h][w]; c1[h] = xp[h][w + 1]; }
        __half* fr = feats + ((size_t)ch * L_SEQ + i) * KF;
        float o0[7], o1[7];

        // branch1: k=3, prelu, maxpool3 -> rows 0..4
        {
            const float* wp = &w1s[ch * 3];
            float bb = b1s[ch];
            #pragma unroll
            for (int h = 0; h < 7; h++) {
                float v0 = bb + wp[0]*c0[h+2] + wp[1]*c0[h+3] + wp[2]*c0[h+4];
                float v1 = bb + wp[0]*c1[h+2] + wp[1]*c1[h+3] + wp[2]*c1[h+4];
                o0[h] = (v0 >= 0.f) ? v0 : a * v0;
                o1[h] = (v1 >= 0.f) ? v1 : a * v1;
            }
            #pragma unroll
            for (int hp = 0; hp < 5; hp++)
                *(__half2*)&fr[hp * CAT_DIM + w] = __floats2half2_rn(
                    fmaxf(fmaxf(o0[hp], o0[hp+1]), o0[hp+2]),
                    fmaxf(fmaxf(o1[hp], o1[hp+1]), o1[hp+2]));
        }
        // branch2: k=5, relu, maxpool5 -> rows 0..2 (offset 540)
        {
            const float* wp = &w2s[ch * 5];
            float bb = b2s[ch];
            #pragma unroll
            for (int h = 0; h < 7; h++) {
                float v0 = bb, v1 = bb;
                #pragma unroll
                for (int tt = 0; tt < 5; tt++) {
                    v0 += wp[tt] * c0[h + 1 + tt];
                    v1 += wp[tt] * c1[h + 1 + tt];
                }
                o0[h] = fmaxf(v0, 0.f); o1[h] = fmaxf(v1, 0.f);
            }
            #pragma unroll
            for (int hp = 0; hp < 3; hp++) {
                float m0 = o0[hp], m1 = o1[hp];
                #pragma unroll
                for (int q = 1; q < 5; q++) { m0 = fmaxf(m0, o0[hp+q]); m1 = fmaxf(m1, o1[hp+q]); }
                *(__half2*)&fr[540 + hp * CAT_DIM + w] = __floats2half2_rn(m0, m1);
            }
        }
        // branch3: k=7, relu, maxpool7 -> 1 row (offset 864)
        {
            const float* wp = &w3s[ch * 7];
            float bb = b3s[ch];
            float m0 = -1e30f, m1 = -1e30f;
            #pragma unroll
            for (int h = 0; h < 7; h++) {
                float v0 = bb, v1 = bb;
                #pragma unroll
                for (int tt = 0; tt < 7; tt++) {
                    v0 += wp[tt] * c0[h + tt];
                    v1 += wp[tt] * c1[h + tt];
                }
                m0 = fmaxf(m0, fmaxf(v0, 0.f));
                m1 = fmaxf(m1, fmaxf(v1, 0.f));
            }
            *(__half2*)&fr[864 + w] = __floats2half2_rn(m0, m1);
        }
    }
}

// ---------------------------------------------------------------------------
// fp16 tensor-core GEMM v2: BK=64, 2-stage cp.async, 64KB dynamic smem.
// EPI 0: store half to Ch.  EPI 1: atomicAdd float into Cf (shared across z).
// ---------------------------------------------------------------------------
#define STAGE_BYTES 16384  // 128*64*2 = 64*128*2

template<int EPI>
__global__ void __launch_bounds__(256, 2) hgemm(
        const __half* __restrict__ A, size_t strideA, int lda, int Mclamp,
        const __half* __restrict__ B, size_t strideB, int KT,
        float* __restrict__ Cf, __half* __restrict__ Ch, size_t strideC) {
    extern __shared__ __align__(16) __half smem[];
    const int tid = threadIdx.x, lane = tid & 31, warp = tid >> 5;
    const int bn = blockIdx.x * 128, bm = blockIdx.y * 128;
    const int z = blockIdx.z;
    A += strideA * z;
    B += strideB * z;
    const int wm = (warp >> 2) * 64, wn = (warp & 3) * 32;
    uint32_t sAu = (uint32_t)__cvta_generic_to_shared(&smem[0]);
    uint32_t sBu = sAu + 2 * STAGE_BYTES;

    float acc[4][4][4] = {};

    auto loadTile = [&](int kt, int st) {
        #pragma unroll
        for (int l = 0; l < 4; l++) {
            int j = tid + l * 256;                 // 1024 chunks: 128 rows x 8
            int r = j >> 3, c = j & 7;
            int gr = min(bm + r, Mclamp - 1);
            const __half* src = A + (size_t)gr * lda + kt * 64 + c * 8;
            int cs = c ^ (r & 7);
            uint32_t dst = sAu + st * STAGE_BYTES + (uint32_t)(r * 64 + cs * 8) * 2;
            asm volatile("cp.async.cg.shared.global [%0], [%1], 16;" :: "r"(dst), "l"(src));
        }
        #pragma unroll
        for (int l = 0; l < 4; l++) {
            int j = tid + l * 256;                 // 1024 chunks: 64 rows x 16
            int r = j >> 4, c = j & 15;
            const __half* src = B + (size_t)(kt * 64 + r) * N_DIM + bn + c * 8;
            int cs = c ^ (r & 7);
            uint32_t dst = sBu + st * STAGE_BYTES + (uint32_t)(r * 128 + cs * 8) * 2;
            asm volatile("cp.async.cg.shared.global [%0], [%1], 16;" :: "r"(dst), "l"(src));
        }
    };

    loadTile(0, 0);
    asm volatile("cp.async.commit_group;");

    for (int kt = 0; kt < KT; kt++) {
        if (kt + 1 < KT) {
            loadTile(kt + 1, (kt + 1) & 1);
            asm volatile("cp.async.commit_group;");
            asm volatile("cp.async.wait_group 1;");
        } else {
            asm volatile("cp.async.wait_group 0;");
        }
        __syncthreads();
        const int st = kt & 1;
        #pragma unroll
        for (int ks = 0; ks < 4; ks++) {          // 4 k16 steps within BK=64
            uint32_t a[4][4], b[4][2];
            #pragma unroll
            for (int mi = 0; mi < 4; mi++) {
                int r = wm + mi * 16 + (lane & 15);
                int cc = ks * 2 + (lane >> 4);
                int cs = cc ^ (r & 7);
                uint32_t addr = sAu + st * STAGE_BYTES + (uint32_t)(r * 64 + cs * 8) * 2;
                asm volatile("ldmatrix.sync.aligned.m8n8.x4.shared.b16 {%0,%1,%2,%3}, [%4];"
                    : "=r"(a[mi][0]), "=r"(a[mi][1]), "=r"(a[mi][2]), "=r"(a[mi][3])
                    : "r"(addr));
            }
            #pragma unroll
            for (int tp = 0; tp < 2; tp++) {
                int kr = ks * 16 + (lane & 15);
                int n0 = wn + (tp * 2 + (lane >> 4)) * 8;
                int cs = (n0 >> 3) ^ (kr & 7);
                uint32_t addr = sBu + st * STAGE_BYTES + (uint32_t)(kr * 128 + cs * 8) * 2;
                asm volatile("ldmatrix.sync.aligned.m8n8.x4.trans.shared.b16 {%0,%1,%2,%3}, [%4];"
                    : "=r"(b[tp*2][0]), "=r"(b[tp*2][1]), "=r"(b[tp*2+1][0]), "=r"(b[tp*2+1][1])
                    : "r"(addr));
            }
            #pragma unroll
            for (int mi = 0; mi < 4; mi++)
                #pragma unroll
                for (int ni = 0; ni < 4; ni++)
                    asm volatile(
                        "mma.sync.aligned.m16n8k16.row.col.f32.f16.f16.f32 "
                        "{%0,%1,%2,%3}, {%4,%5,%6,%7}, {%8,%9}, {%0,%1,%2,%3};"
                        : "+f"(acc[mi][ni][0]), "+f"(acc[mi][ni][1]),
                          "+f"(acc[mi][ni][2]), "+f"(acc[mi][ni][3])
                        : "r"(a[mi][0]), "r"(a[mi][1]), "r"(a[mi][2]), "r"(a[mi][3]),
                          "r"(b[ni][0]), "r"(b[ni][1]));
        }
        __syncthreads();
    }

    #pragma unroll
    for (int mi = 0; mi < 4; mi++) {
        int r0 = bm + wm + mi * 16 + (lane >> 2);
        #pragma unroll
        for (int ni = 0; ni < 4; ni++) {
            int col = bn + wn + ni * 8 + (lane & 3) * 2;
            if (EPI == 0) {
                __half* base = Ch + strideC * z;
                *(__half2*)(base + (size_t)r0 * N_DIM + col) =
                    __floats2half2_rn(acc[mi][ni][0], acc[mi][ni][1]);
                *(__half2*)(base + (size_t)(r0 + 8) * N_DIM + col) =
                    __floats2half2_rn(acc[mi][ni][2], acc[mi][ni][3]);
            } else {
                if (r0 < Mclamp) {
                    atomicAdd(&Cf[(size_t)r0 * N_DIM + col],     acc[mi][ni][0]);
                    atomicAdd(&Cf[(size_t)r0 * N_DIM + col + 1], acc[mi][ni][1]);
                }
                if (r0 + 8 < Mclamp) {
                    atomicAdd(&Cf[(size_t)(r0 + 8) * N_DIM + col],     acc[mi][ni][2]);
                    atomicAdd(&Cf[(size_t)(r0 + 8) * N_DIM + col + 1], acc[mi][ni][3]);
                }
            }
        }
    }
}

// ---------------------------------------------------------------------------
// Final: in-place leaky relu on out
// ---------------------------------------------------------------------------
__global__ void leaky_inplace(float* __restrict__ out) {
    int idx = blockIdx.x * 256 + threadIdx.x;
    if (idx < L_SEQ * N_DIM) {
        float s = out[idx];
        out[idx] = (s >= 0.f) ? s : 0.01f * s;
    }
}

// ---------------------------------------------------------------------------
extern "C" void kernel_launch(void* const* d_in, const int* in_sizes, int n_in,
                              void* d_out, int out_size) {
    const float* beft   = (const float*)d_in[0];
    const float* Wb     = (const float*)d_in[4];
    const float* bb     = (const float*)d_in[5];
    const float* ln_g1  = (const float*)d_in[6];
    const float* ln_b1  = (const float*)d_in[7];
    const float* ln_g2  = (const float*)d_in[8];
    const float* ln_b2  = (const float*)d_in[9];
    const float* cw1    = (const float*)d_in[10];
    const float* cb1    = (const float*)d_in[11];
    const float* pa     = (const float*)d_in[12];
    const float* cw2    = (const float*)d_in[13];
    const float* cb2    = (const float*)d_in[14];
    const float* cw3    = (const float*)d_in[15];
    const float* cb3    = (const float*)d_in[16];
    const float* W1     = (const float*)d_in[17];
    const float* b1     = (const float*)d_in[18];
    const float* W2     = (const float*)d_in[19];
    const float* b2     = (const float*)d_in[20];
    float* out = (float*)d_out;

    float* f   = nullptr; cudaGetSymbolAddress((void**)&f, g_f);
    float* cat = nullptr; cudaGetSymbolAddress((void**)&cat, g_cat);
    __half* feats = nullptr; cudaGetSymbolAddress((void**)&feats, g_featsq);
    __half* w1h   = nullptr; cudaGetSymbolAddress((void**)&w1h, g_w1hq);
    __half* w2h   = nullptr; cudaGetSymbolAddress((void**)&w2h, g_w2hq);
    __half* wch   = nullptr; cudaGetSymbolAddress((void**)&wch, g_wchq);
    float* bcp    = nullptr; cudaGetSymbolAddress((void**)&bcp, g_bcp);

    const int SMEM = 4 * STAGE_BYTES;  // 64KB
    cudaFuncSetAttribute(hgemm<0>, cudaFuncAttributeMaxDynamicSharedMemorySize, SMEM);
    cudaFuncSetAttribute(hgemm<1>, cudaFuncAttributeMaxDynamicSharedMemorySize, SMEM);

    // Weight prep + bias folding + out init
    {
        int total = KF * N_DIM + CH_CONV * N_DIM * N_DIM;
        prep_weights<<<(total + 255) / 256, 256>>>(W1, w1h, W2, w2h);
    }
    bc_partial<<<CH_CONV, 256>>>(b1, W2, bcp);
    init_out<<<(L_SEQ * N_DIM + 255) / 256, 256>>>(bcp, b2, out);

    // Wc[ch] = W1h(1024x256) @ W2h[ch](256x256), output fp16
    {
        dim3 grid(2, 8, CH_CONV);
        hgemm<0><<<grid, 256, SMEM>>>(w1h, 0, N_DIM, KF,
                                      w2h, (size_t)N_DIM * N_DIM, N_DIM / 64,
                                      nullptr, wch, (size_t)KF * N_DIM);
    }

    // Activations
    bert_kernel<<<L_SEQ / 4, 256>>>(beft, Wb, bb, f);
    attn_kernel<<<L_SEQ / 8, 256>>>(f, ln_g1, ln_b1, ln_g2, ln_b2, cat);
    conv_kernel<<<L_SEQ, 256>>>(cat, cw1, cb1, pa, cw2, cb2, cw3, cb3, feats);

    // Main GEMM per ch: out += feats[ch](2000x1024) @ Wc[ch](1024x256)
    {
        dim3 grid(2, 16, CH_CONV);
        hgemm<1><<<grid, 256, SMEM>>>(feats, (size_t)L_SEQ * KF, KF, L_SEQ,
                                      wch, (size_t)KF * N_DIM, KF / 64,
                                      out, nullptr, 0);
    }

    // out = leaky(out)
    leaky_inplace<<<(L_SEQ * N_DIM + 255) / 256, 256>>>(out);
}

// round 8
// speedup vs baseline: 7.2940x; 1.1040x over previous
#include <cuda_runtime.h>
#include <cuda_fp16.h>
#include <cstdint>
#include <math.h>

// Problem constants
#define L_SEQ 2000
#define D_FEAT 54
#define W_WIN 7
#define H_HEADS 3
#define HD_DIM 18
#define CH_CONV 32
#define CAT_DIM 108        // 2*D
#define K1_DIM 972         // real feature dim
#define KF 1024            // padded feature dim
#define N_DIM 256

// Scratch (device globals; no allocations allowed). uint4 for 16B alignment.
__device__ float g_f[L_SEQ * D_FEAT];
__device__ float g_cat[L_SEQ * W_WIN * CAT_DIM];
__device__ uint4 g_featsq[(size_t)CH_CONV * L_SEQ * KF / 8];   // half[32][2000][1024] ~131MB
__device__ uint4 g_w1hq[(size_t)KF * N_DIM / 8];               // half[1024][256]
__device__ uint4 g_w2hq[(size_t)CH_CONV * N_DIM * N_DIM / 8];  // half[8192][256]
__device__ uint4 g_wchq[(size_t)CH_CONV * KF * N_DIM / 8];     // half[32][1024][256]
__device__ float g_bcp[CH_CONV * N_DIM];

// ---------------------------------------------------------------------------
// Prep: round W1 (padded) and W2 to fp16, one kernel.
// ---------------------------------------------------------------------------
__global__ void prep_weights(const float* __restrict__ W1, __half* __restrict__ W1h,
                             const float* __restrict__ W2, __half* __restrict__ W2h) {
    int idx = blockIdx.x * 256 + threadIdx.x;
    if (idx < KF * N_DIM) {
        int k = idx >> 8;
        W1h[idx] = (k < K1_DIM) ? __float2half(W1[idx]) : __half(0.f);
    }
    int idx2 = idx - KF * N_DIM;
    if (idx2 >= 0 && idx2 < CH_CONV * N_DIM * N_DIM) W2h[idx2] = __float2half(W2[idx2]);
}

// bcp[ch][n] = sum_m b1[m] * W2[ch*256+m, n]
__global__ void bc_partial(const float* __restrict__ b1, const float* __restrict__ W2,
                           float* __restrict__ bcp) {
    int ch = blockIdx.x, n = threadIdx.x;
    float s = 0.f;
    for (int m = 0; m < 256; m++) s += b1[m] * W2[((size_t)ch * 256 + m) * 256 + n];
    bcp[ch * 256 + n] = s;
}

// out[i,n] = b2[n] + sum_ch bcp[ch,n]   (init accumulator with folded bias)
__global__ void init_out(const float* __restrict__ bcp, const float* __restrict__ b2,
                         float* __restrict__ out) {
    int idx = blockIdx.x * 256 + threadIdx.x;
    if (idx < L_SEQ * N_DIM) {
        int n = idx & 255;
        float s = b2[n];
        #pragma unroll
        for (int ch = 0; ch < 32; ch++) s += bcp[ch * 256 + n];
        out[idx] = s;
    }
}

// ---------------------------------------------------------------------------
// Kernel A: f = beft @ W_bert + b_bert     (2000,1024)@(1024,54)
// ---------------------------------------------------------------------------
__global__ void __launch_bounds__(256) bert_kernel(
        const float* __restrict__ beft, const float* __restrict__ Wb,
        const float* __restrict__ bb, float* __restrict__ f) {
    __shared__ float sh[4][1024];
    __shared__ float red[4][4][64];
    int r0 = blockIdx.x * 4;
    int tid = threadIdx.x;
    for (int idx = tid; idx < 4 * 1024; idx += 256)
        sh[idx >> 10][idx & 1023] = beft[(r0 + (idx >> 10)) * 1024 + (idx & 1023)];
    __syncthreads();
    int col = tid & 63;
    int ks = tid >> 6;
    float acc[4] = {0.f, 0.f, 0.f, 0.f};
    if (col < D_FEAT) {
        int kend = ks * 256 + 256;
        for (int k = ks * 256; k < kend; k++) {
            float w = Wb[k * D_FEAT + col];
            #pragma unroll
            for (int r = 0; r < 4; r++) acc[r] += sh[r][k] * w;
        }
    }
    #pragma unroll
    for (int r = 0; r < 4; r++) red[ks][r][col] = acc[r];
    __syncthreads();
    if (ks == 0 && col < D_FEAT) {
        float bias = bb[col];
        #pragma unroll
        for (int r = 0; r < 4; r++)
            f[(r0 + r) * D_FEAT + col] =
                red[0][r][col] + red[1][r][col] + red[2][r][col] + red[3][r][col] + bias;
    }
}

// ---------------------------------------------------------------------------
// Kernel B: warp-per-residue attention (2 passes) -> cat
// ---------------------------------------------------------------------------
__global__ void __launch_bounds__(256) attn_kernel(
        const float* __restrict__ f,
        const float* __restrict__ g1, const float* __restrict__ be1,
        const float* __restrict__ g2, const float* __restrict__ be2,
        float* __restrict__ cat) {
    __shared__ float X[8][W_WIN][D_FEAT];
    __shared__ float NF[8][W_WIN][D_FEAT];
    __shared__ float P[8][H_HEADS][49];
    __shared__ float O[8][W_WIN][D_FEAT];

    int w = threadIdx.x >> 5, lane = threadIdx.x & 31;
    int i = blockIdx.x * 8 + w;
    float (*x)[D_FEAT] = X[w];
    float (*nf)[D_FEAT] = NF[w];
    float (*p)[49] = P[w];
    float (*o)[D_FEAT] = O[w];

    bool boundary = (i <= W_WIN) || (i + W_WIN >= L_SEQ);
    for (int e = lane; e < W_WIN * D_FEAT; e += 32) {
        int q = e / D_FEAT, c = e % D_FEAT;
        float v;
        if (boundary) v = (q == 0) ? f[i * D_FEAT + c] : 0.f;
        else          v = f[(i - 4 + q) * D_FEAT + c];
        x[q][c] = v; nf[q][c] = v;
    }
    __syncwarp();

    #pragma unroll
    for (int pass = 0; pass < 2; pass++) {
        const float* g  = pass ? g2 : g1;
        const float* bb = pass ? be2 : be1;
        for (int e = lane; e < H_HEADS * 49; e += 32) {
            int h = e / 49, r = e % 49, q = r / 7, k = r % 7;
            float s = 0.f;
            #pragma unroll
            for (int d = 0; d < HD_DIM; d++)
                s += x[q][h * HD_DIM + d] * x[k][h * HD_DIM + d];
            p[h][r] = s;
        }
        __syncwarp();
        if (lane < H_HEADS * W_WIN) {
            int h = lane / 7, q = lane % 7;
            float* pr = &p[h][q * 7];
            float mx = -1e30f;
            #pragma unroll
            for (int k = 0; k < 7; k++) mx = fmaxf(mx, pr[k]);
            float e[7], sum = 0.f;
            #pragma unroll
            for (int k = 0; k < 7; k++) { e[k] = expf(pr[k] - mx); sum += e[k]; }
            float inv = 1.f / sum;
            #pragma unroll
            for (int k = 0; k < 7; k++) pr[k] = e[k] * inv;
        }
        __syncwarp();
        for (int e = lane; e < W_WIN * D_FEAT; e += 32) {
            int q = e / D_FEAT, c = e % D_FEAT, h = c / HD_DIM;
            const float* pr = &p[h][q * 7];
            float s = 0.f;
            #pragma unroll
            for (int k = 0; k < 7; k++) s += pr[k] * x[k][c];
            o[q][c] = s;
        }
        __syncwarp();
        if (lane < W_WIN) {
            int q = lane;
            float m = 0.f;
            #pragma unroll
            for (int c = 0; c < D_FEAT; c++) m += o[q][c];
            m *= (1.f / D_FEAT);
            float v = 0.f;
            #pragma unroll
            for (int c = 0; c < D_FEAT; c++) { float d = o[q][c] - m; v += d * d; }
            v *= (1.f / D_FEAT);
            float r = rsqrtf(v + 1e-5f);
            #pragma unroll
            for (int c = 0; c < D_FEAT; c++)
                x[q][c] = (o[q][c] - m) * r * g[c] + bb[c];
        }
        __syncwarp();
    }

    for (int e = lane; e < W_WIN * CAT_DIM; e += 32) {
        int q = e / CAT_DIM, c = e % CAT_DIM;
        cat[i * (W_WIN * CAT_DIM) + e] = (c < D_FEAT) ? nf[q][c] : x[q][c - D_FEAT];
    }
}

// ---------------------------------------------------------------------------
// Kernel C: conv branches + act + maxpool -> feats fp16, layout [ch][i][KF]
// ---------------------------------------------------------------------------
__global__ void __launch_bounds__(256) conv_kernel(
        const float* __restrict__ cat,
        const float* __restrict__ cw1, const float* __restrict__ cb1,
        const float* __restrict__ pa,
        const float* __restrict__ cw2, const float* __restrict__ cb2,
        const float* __restrict__ cw3, const float* __restrict__ cb3,
        __half* __restrict__ feats) {
    int i = blockIdx.x;
    int t = threadIdx.x;
    __shared__ float xp[13][CAT_DIM];
    __shared__ float w1s[96], w2s[160], w3s[224];
    __shared__ float b1s[32], b2s[32], b3s[32];

    for (int idx = t; idx < 13 * CAT_DIM; idx += 256) {
        int h = idx / CAT_DIM, w = idx % CAT_DIM;
        xp[h][w] = (h >= 3 && h < 10) ? cat[i * (W_WIN * CAT_DIM) + (h - 3) * CAT_DIM + w] : 0.f;
    }
    if (t < 96)  w1s[t] = cw1[t];
    if (t < 160) w2s[t] = cw2[t];
    if (t < 224) w3s[t] = cw3[t];
    if (t < 32) { b1s[t] = cb1[t]; b2s[t] = cb2[t]; b3s[t] = cb3[t]; }
    float a = *pa;
    __syncthreads();

    for (int idx = t; idx < CH_CONV * (KF - K1_DIM) / 2; idx += 256) {
        int ch = idx / 26, c = idx % 26;
        *(__half2*)&feats[((size_t)ch * L_SEQ + i) * KF + K1_DIM + c * 2] =
            __floats2half2_rn(0.f, 0.f);
    }

    for (int pp = t; pp < CH_CONV * (CAT_DIM / 2); pp += 256) {
        int ch = pp / (CAT_DIM / 2), w = (pp % (CAT_DIM / 2)) * 2;
        float c0[13], c1[13];
        #pragma unroll
        for (int h = 0; h < 13; h++) { c0[h] = xp[h][w]; c1[h] = xp[h][w + 1]; }
        __half* fr = feats + ((size_t)ch * L_SEQ + i) * KF;
        float o0[7], o1[7];

        // branch1: k=3, prelu, maxpool3 -> rows 0..4
        {
            const float* wp = &w1s[ch * 3];
            float bb = b1s[ch];
            #pragma unroll
            for (int h = 0; h < 7; h++) {
                float v0 = bb + wp[0]*c0[h+2] + wp[1]*c0[h+3] + wp[2]*c0[h+4];
                float v1 = bb + wp[0]*c1[h+2] + wp[1]*c1[h+3] + wp[2]*c1[h+4];
                o0[h] = (v0 >= 0.f) ? v0 : a * v0;
                o1[h] = (v1 >= 0.f) ? v1 : a * v1;
            }
            #pragma unroll
            for (int hp = 0; hp < 5; hp++)
                *(__half2*)&fr[hp * CAT_DIM + w] = __floats2half2_rn(
                    fmaxf(fmaxf(o0[hp], o0[hp+1]), o0[hp+2]),
                    fmaxf(fmaxf(o1[hp], o1[hp+1]), o1[hp+2]));
        }
        // branch2: k=5, relu, maxpool5 -> rows 0..2 (offset 540)
        {
            const float* wp = &w2s[ch * 5];
            float bb = b2s[ch];
            #pragma unroll
            for (int h = 0; h < 7; h++) {
                float v0 = bb, v1 = bb;
                #pragma unroll
                for (int tt = 0; tt < 5; tt++) {
                    v0 += wp[tt] * c0[h + 1 + tt];
                    v1 += wp[tt] * c1[h + 1 + tt];
                }
                o0[h] = fmaxf(v0, 0.f); o1[h] = fmaxf(v1, 0.f);
            }
            #pragma unroll
            for (int hp = 0; hp < 3; hp++) {
                float m0 = o0[hp], m1 = o1[hp];
                #pragma unroll
                for (int q = 1; q < 5; q++) { m0 = fmaxf(m0, o0[hp+q]); m1 = fmaxf(m1, o1[hp+q]); }
                *(__half2*)&fr[540 + hp * CAT_DIM + w] = __floats2half2_rn(m0, m1);
            }
        }
        // branch3: k=7, relu, maxpool7 -> 1 row (offset 864)
        {
            const float* wp = &w3s[ch * 7];
            float bb = b3s[ch];
            float m0 = -1e30f, m1 = -1e30f;
            #pragma unroll
            for (int h = 0; h < 7; h++) {
                float v0 = bb, v1 = bb;
                #pragma unroll
                for (int tt = 0; tt < 7; tt++) {
                    v0 += wp[tt] * c0[h + tt];
                    v1 += wp[tt] * c1[h + tt];
                }
                m0 = fmaxf(m0, fmaxf(v0, 0.f));
                m1 = fmaxf(m1, fmaxf(v1, 0.f));
            }
            *(__half2*)&fr[864 + w] = __floats2half2_rn(m0, m1);
        }
    }
}

// ---------------------------------------------------------------------------
// fp16 tensor-core GEMM: BK=64, 3-stage cp.async, 96KB dynamic smem.
// EPI 0: store half to Ch.  EPI 1: atomicAdd float into Cf (shared across z).
// ---------------------------------------------------------------------------
#define STAGE_BYTES 16384  // per-operand per-stage: 128*64*2 == 64*128*2
#define HG_SMEM (6 * STAGE_BYTES)

template<int EPI>
__global__ void __launch_bounds__(256, 2) hgemm(
        const __half* __restrict__ A, size_t strideA, int lda, int Mclamp,
        const __half* __restrict__ B, size_t strideB, int KT,
        float* __restrict__ Cf, __half* __restrict__ Ch, size_t strideC) {
    extern __shared__ __align__(16) __half smem[];
    const int tid = threadIdx.x, lane = tid & 31, warp = tid >> 5;
    const int bn = blockIdx.x * 128, bm = blockIdx.y * 128;
    const int z = blockIdx.z;
    A += strideA * z;
    B += strideB * z;
    const int wm = (warp >> 2) * 64, wn = (warp & 3) * 32;
    uint32_t sAu = (uint32_t)__cvta_generic_to_shared(&smem[0]);
    uint32_t sBu = sAu + 3 * STAGE_BYTES;

    float acc[4][4][4] = {};

    auto loadTile = [&](int kt, int st) {
        #pragma unroll
        for (int l = 0; l < 4; l++) {
            int j = tid + l * 256;                 // 1024 chunks: 128 rows x 8
            int r = j >> 3, c = j & 7;
            int gr = min(bm + r, Mclamp - 1);
            const __half* src = A + (size_t)gr * lda + kt * 64 + c * 8;
            int cs = c ^ (r & 7);
            uint32_t dst = sAu + st * STAGE_BYTES + (uint32_t)(r * 64 + cs * 8) * 2;
            asm volatile("cp.async.cg.shared.global [%0], [%1], 16;" :: "r"(dst), "l"(src));
        }
        #pragma unroll
        for (int l = 0; l < 4; l++) {
            int j = tid + l * 256;                 // 1024 chunks: 64 rows x 16
            int r = j >> 4, c = j & 15;
            const __half* src = B + (size_t)(kt * 64 + r) * N_DIM + bn + c * 8;
            int cs = c ^ (r & 7);
            uint32_t dst = sBu + st * STAGE_BYTES + (uint32_t)(r * 128 + cs * 8) * 2;
            asm volatile("cp.async.cg.shared.global [%0], [%1], 16;" :: "r"(dst), "l"(src));
        }
    };

    loadTile(0, 0);
    asm volatile("cp.async.commit_group;");
    if (KT > 1) { loadTile(1, 1); }
    asm volatile("cp.async.commit_group;");

    for (int kt = 0; kt < KT; kt++) {
        if (kt + 2 < KT) {
            loadTile(kt + 2, (kt + 2) % 3);
            asm volatile("cp.async.commit_group;");
            asm volatile("cp.async.wait_group 2;");
        } else if (kt + 2 == KT) {
            asm volatile("cp.async.wait_group 1;");
        } else {
            asm volatile("cp.async.wait_group 0;");
        }
        __syncthreads();
        const int st = kt % 3;
        #pragma unroll
        for (int ks = 0; ks < 4; ks++) {          // 4 k16 steps within BK=64
            uint32_t a[4][4], b[4][2];
            #pragma unroll
            for (int mi = 0; mi < 4; mi++) {
                int r = wm + mi * 16 + (lane & 15);
                int cc = ks * 2 + (lane >> 4);
                int cs = cc ^ (r & 7);
                uint32_t addr = sAu + st * STAGE_BYTES + (uint32_t)(r * 64 + cs * 8) * 2;
                asm volatile("ldmatrix.sync.aligned.m8n8.x4.shared.b16 {%0,%1,%2,%3}, [%4];"
                    : "=r"(a[mi][0]), "=r"(a[mi][1]), "=r"(a[mi][2]), "=r"(a[mi][3])
                    : "r"(addr));
            }
            #pragma unroll
            for (int tp = 0; tp < 2; tp++) {
                int kr = ks * 16 + (lane & 15);
                int n0 = wn + (tp * 2 + (lane >> 4)) * 8;
                int cs = (n0 >> 3) ^ (kr & 7);
                uint32_t addr = sBu + st * STAGE_BYTES + (uint32_t)(kr * 128 + cs * 8) * 2;
                asm volatile("ldmatrix.sync.aligned.m8n8.x4.trans.shared.b16 {%0,%1,%2,%3}, [%4];"
                    : "=r"(b[tp*2][0]), "=r"(b[tp*2][1]), "=r"(b[tp*2+1][0]), "=r"(b[tp*2+1][1])
                    : "r"(addr));
            }
            #pragma unroll
            for (int mi = 0; mi < 4; mi++)
                #pragma unroll
                for (int ni = 0; ni < 4; ni++)
                    asm volatile(
                        "mma.sync.aligned.m16n8k16.row.col.f32.f16.f16.f32 "
                        "{%0,%1,%2,%3}, {%4,%5,%6,%7}, {%8,%9}, {%0,%1,%2,%3};"
                        : "+f"(acc[mi][ni][0]), "+f"(acc[mi][ni][1]),
                          "+f"(acc[mi][ni][2]), "+f"(acc[mi][ni][3])
                        : "r"(a[mi][0]), "r"(a[mi][1]), "r"(a[mi][2]), "r"(a[mi][3]),
                          "r"(b[ni][0]), "r"(b[ni][1]));
        }
        __syncthreads();
    }

    #pragma unroll
    for (int mi = 0; mi < 4; mi++) {
        int r0 = bm + wm + mi * 16 + (lane >> 2);
        #pragma unroll
        for (int ni = 0; ni < 4; ni++) {
            int col = bn + wn + ni * 8 + (lane & 3) * 2;
            if (EPI == 0) {
                __half* base = Ch + strideC * z;
                *(__half2*)(base + (size_t)r0 * N_DIM + col) =
                    __floats2half2_rn(acc[mi][ni][0], acc[mi][ni][1]);
                *(__half2*)(base + (size_t)(r0 + 8) * N_DIM + col) =
                    __floats2half2_rn(acc[mi][ni][2], acc[mi][ni][3]);
            } else {
                if (r0 < Mclamp) {
                    atomicAdd(&Cf[(size_t)r0 * N_DIM + col],     acc[mi][ni][0]);
                    atomicAdd(&Cf[(size_t)r0 * N_DIM + col + 1], acc[mi][ni][1]);
                }
                if (r0 + 8 < Mclamp) {
                    atomicAdd(&Cf[(size_t)(r0 + 8) * N_DIM + col],     acc[mi][ni][2]);
                    atomicAdd(&Cf[(size_t)(r0 + 8) * N_DIM + col + 1], acc[mi][ni][3]);
                }
            }
        }
    }
}

// ---------------------------------------------------------------------------
// Final: in-place leaky relu on out
// ---------------------------------------------------------------------------
__global__ void leaky_inplace(float* __restrict__ out) {
    int idx = blockIdx.x * 256 + threadIdx.x;
    if (idx < L_SEQ * N_DIM) {
        float s = out[idx];
        out[idx] = (s >= 0.f) ? s : 0.01f * s;
    }
}

// ---------------------------------------------------------------------------
extern "C" void kernel_launch(void* const* d_in, const int* in_sizes, int n_in,
                              void* d_out, int out_size) {
    const float* beft   = (const float*)d_in[0];
    const float* Wb     = (const float*)d_in[4];
    const float* bb     = (const float*)d_in[5];
    const float* ln_g1  = (const float*)d_in[6];
    const float* ln_b1  = (const float*)d_in[7];
    const float* ln_g2  = (const float*)d_in[8];
    const float* ln_b2  = (const float*)d_in[9];
    const float* cw1    = (const float*)d_in[10];
    const float* cb1    = (const float*)d_in[11];
    const float* pa     = (const float*)d_in[12];
    const float* cw2    = (const float*)d_in[13];
    const float* cb2    = (const float*)d_in[14];
    const float* cw3    = (const float*)d_in[15];
    const float* cb3    = (const float*)d_in[16];
    const float* W1     = (const float*)d_in[17];
    const float* b1     = (const float*)d_in[18];
    const float* W2     = (const float*)d_in[19];
    const float* b2     = (const float*)d_in[20];
    float* out = (float*)d_out;

    float* f   = nullptr; cudaGetSymbolAddress((void**)&f, g_f);
    float* cat = nullptr; cudaGetSymbolAddress((void**)&cat, g_cat);
    __half* feats = nullptr; cudaGetSymbolAddress((void**)&feats, g_featsq);
    __half* w1h   = nullptr; cudaGetSymbolAddress((void**)&w1h, g_w1hq);
    __half* w2h   = nullptr; cudaGetSymbolAddress((void**)&w2h, g_w2hq);
    __half* wch   = nullptr; cudaGetSymbolAddress((void**)&wch, g_wchq);
    float* bcp    = nullptr; cudaGetSymbolAddress((void**)&bcp, g_bcp);

    cudaFuncSetAttribute(hgemm<0>, cudaFuncAttributeMaxDynamicSharedMemorySize, HG_SMEM);
    cudaFuncSetAttribute(hgemm<1>, cudaFuncAttributeMaxDynamicSharedMemorySize, HG_SMEM);

    // Side stream + events, created once outside capture (first call is the
    // correctness run; capture happens on a later call).
    static cudaStream_t s2 = nullptr;
    static cudaEvent_t eFork = nullptr, eJoin = nullptr;
    if (!s2) {
        cudaStreamCreateWithFlags(&s2, cudaStreamNonBlocking);
        cudaEventCreateWithFlags(&eFork, cudaEventDisableTiming);
        cudaEventCreateWithFlags(&eJoin, cudaEventDisableTiming);
    }

    // Fork: weight-prep chain on s2, activation chain on the default stream.
    cudaEventRecord(eFork, 0);
    cudaStreamWaitEvent(s2, eFork, 0);

    // --- s2: weight prep + bias folding + out init + Wc GEMM ---
    {
        int total = KF * N_DIM + CH_CONV * N_DIM * N_DIM;
        prep_weights<<<(total + 255) / 256, 256, 0, s2>>>(W1, w1h, W2, w2h);
    }
    bc_partial<<<CH_CONV, 256, 0, s2>>>(b1, W2, bcp);
    init_out<<<(L_SEQ * N_DIM + 255) / 256, 256, 0, s2>>>(bcp, b2, out);
    {
        dim3 grid(2, 8, CH_CONV);   // FULL N coverage (bugfix from R7)
        hgemm<0><<<grid, 256, HG_SMEM, s2>>>(w1h, 0, N_DIM, KF,
                                             w2h, (size_t)N_DIM * N_DIM, N_DIM / 64,
                                             nullptr, wch, (size_t)KF * N_DIM);
    }
    cudaEventRecord(eJoin, s2);

    // --- default stream: activations ---
    bert_kernel<<<L_SEQ / 4, 256>>>(beft, Wb, bb, f);
    attn_kernel<<<L_SEQ / 8, 256>>>(f, ln_g1, ln_b1, ln_g2, ln_b2, cat);
    conv_kernel<<<L_SEQ, 256>>>(cat, cw1, cb1, pa, cw2, cb2, cw3, cb3, feats);

    // Join, then main GEMM per ch: out += feats[ch](2000x1024) @ Wc[ch](1024x256)
    cudaStreamWaitEvent(0, eJoin, 0);
    {
        dim3 grid(2, 16, CH_CONV);
        hgemm<1><<<grid, 256, HG_SMEM>>>(feats, (size_t)L_SEQ * KF, KF, L_SEQ,
                                         wch, (size_t)KF * N_DIM, KF / 64,
                                         out, nullptr, 0);
    }

    // out = leaky(out)
    leaky_inplace<<<(L_SEQ * N_DIM + 255) / 256, 256>>>(out);
}